// round 5
// baseline (speedup 1.0000x reference)
#include <cuda_runtime.h>
#include <cuda_bf16.h>
#include <cstdint>

#define B_ 8
#define L_ 2048
#define V_ 10000
#define H_ 512

static const long long LH = (long long)L_ * H_;       // 1048576
static const long long LL = (long long)L_ * L_;       // 4194304

// ---------------- static device scratch (no allocations) ----------------
__device__ float g_embproj[V_ * H_];                   // 20.5 MB
__device__ float g_z[B_ * L_ * H_];                    // 33.5 MB
__device__ float g_P[(size_t)B_ * L_ * L_];            // 134 MB
__device__ float g_av[B_ * L_ * H_];                   // 33.5 MB
__device__ float g_dec[B_ * L_ * H_];                  // 33.5 MB
__device__ __nv_bfloat16 g_dec_hi[B_ * L_ * H_];       // 16.8 MB
__device__ __nv_bfloat16 g_dec_lo[B_ * L_ * H_];       // 16.8 MB
__device__ __nv_bfloat16 g_wd_hi[V_ * H_];             // 10.2 MB
__device__ __nv_bfloat16 g_wd_lo[V_ * H_];             // 10.2 MB

__device__ __forceinline__ uint32_t smem_u32(const void* p) {
    uint32_t a;
    asm("{ .reg .u64 t; cvta.to.shared.u64 t, %1; cvt.u32.u64 %0, t; }"
        : "=r"(a) : "l"(p));
    return a;
}

#define LDSM_X4(r0, r1, r2, r3, addr)                                         \
    asm volatile("ldmatrix.sync.aligned.m8n8.x4.shared.b16 {%0,%1,%2,%3}, [%4];" \
                 : "=r"(r0), "=r"(r1), "=r"(r2), "=r"(r3) : "r"(addr))
#define LDSM_X2(r0, r1, addr)                                                 \
    asm volatile("ldmatrix.sync.aligned.m8n8.x2.shared.b16 {%0,%1}, [%2];"    \
                 : "=r"(r0), "=r"(r1) : "r"(addr))
#define MMA_BF16(c, a, b)                                                     \
    asm volatile("mma.sync.aligned.m16n8k16.row.col.f32.bf16.bf16.f32 "       \
                 "{%0,%1,%2,%3}, {%4,%5,%6,%7}, {%8,%9}, {%0,%1,%2,%3};"      \
                 : "+f"((c)[0]), "+f"((c)[1]), "+f"((c)[2]), "+f"((c)[3])     \
                 : "r"((a)[0]), "r"((a)[1]), "r"((a)[2]), "r"((a)[3]),        \
                   "r"((b)[0]), "r"((b)[1]))

// ======================================================================
// fp32 NT GEMM: C[M,N] = A[M,K] * B[N,K]^T (+bias) (+=C)
// flags: bit0 = accumulate into C, bit1 = causal tile skip (skip bx > by)
// ======================================================================
__global__ __launch_bounds__(256) void gemm_nt(
    const float* __restrict__ A, int lda, long long sA,
    const float* __restrict__ B, int ldb, long long sB,
    float* __restrict__ C, int ldc, long long sC,
    int M, int N, int K,
    const float* __restrict__ bias, int flags)
{
    if ((flags & 2) && blockIdx.x > blockIdx.y) return;
    A += (long long)blockIdx.z * sA;
    B += (long long)blockIdx.z * sB;
    C += (long long)blockIdx.z * sC;

    __shared__ float As[16][128];
    __shared__ float Bs[16][128];

    const int tid = threadIdx.x;
    const int m0 = blockIdx.y * 128;
    const int n0 = blockIdx.x * 128;

    const int lr = tid >> 1;
    const int lk = (tid & 1) << 3;
    const float* Ap = A + (long long)(m0 + lr) * lda + lk;
    const float* Bp = B + (long long)(n0 + lr) * ldb + lk;
    const bool aok = (m0 + lr) < M;
    const bool bok = (n0 + lr) < N;

    const int tr = (tid >> 4) << 3;
    const int tc = (tid & 15) << 3;

    float acc[8][8];
#pragma unroll
    for (int i = 0; i < 8; i++)
#pragma unroll
        for (int j = 0; j < 8; j++) acc[i][j] = 0.f;

    for (int k0 = 0; k0 < K; k0 += 16) {
        float4 a0 = make_float4(0.f,0.f,0.f,0.f), a1 = a0, b0 = a0, b1 = a0;
        if (aok) { a0 = *(const float4*)(Ap + k0); a1 = *(const float4*)(Ap + k0 + 4); }
        if (bok) { b0 = *(const float4*)(Bp + k0); b1 = *(const float4*)(Bp + k0 + 4); }

        As[lk+0][lr]=a0.x; As[lk+1][lr]=a0.y; As[lk+2][lr]=a0.z; As[lk+3][lr]=a0.w;
        As[lk+4][lr]=a1.x; As[lk+5][lr]=a1.y; As[lk+6][lr]=a1.z; As[lk+7][lr]=a1.w;
        Bs[lk+0][lr]=b0.x; Bs[lk+1][lr]=b0.y; Bs[lk+2][lr]=b0.z; Bs[lk+3][lr]=b0.w;
        Bs[lk+4][lr]=b1.x; Bs[lk+5][lr]=b1.y; Bs[lk+6][lr]=b1.z; Bs[lk+7][lr]=b1.w;
        __syncthreads();

#pragma unroll
        for (int kk = 0; kk < 16; kk++) {
            float4 x0 = *(const float4*)&As[kk][tr];
            float4 x1 = *(const float4*)&As[kk][tr + 4];
            float4 y0 = *(const float4*)&Bs[kk][tc];
            float4 y1 = *(const float4*)&Bs[kk][tc + 4];
            float av_[8] = {x0.x,x0.y,x0.z,x0.w,x1.x,x1.y,x1.z,x1.w};
            float bv_[8] = {y0.x,y0.y,y0.z,y0.w,y1.x,y1.y,y1.z,y1.w};
#pragma unroll
            for (int i = 0; i < 8; i++)
#pragma unroll
                for (int j = 0; j < 8; j++)
                    acc[i][j] = fmaf(av_[i], bv_[j], acc[i][j]);
        }
        __syncthreads();
    }

#pragma unroll
    for (int i = 0; i < 8; i++) {
        const int r = m0 + tr + i;
        if (r >= M) continue;
        float* Crow = C + (long long)r * ldc;
#pragma unroll
        for (int jj = 0; jj < 2; jj++) {
            const int c = n0 + tc + jj * 4;
            if (c >= N) continue;
            float4 v;
            v.x = acc[i][jj*4+0]; v.y = acc[i][jj*4+1];
            v.z = acc[i][jj*4+2]; v.w = acc[i][jj*4+3];
            if (bias) { v.x += bias[c]; v.y += bias[c+1]; v.z += bias[c+2]; v.w += bias[c+3]; }
            if (flags & 1) {
                float4 o = *(const float4*)(Crow + c);
                v.x += o.x; v.y += o.y; v.z += o.z; v.w += o.w;
            }
            *(float4*)(Crow + c) = v;
        }
    }
}

// ======================================================================
// fp32 NN GEMM: C[M,N] = A[M,K] * B[K,N]   (klimit for causal P @ z)
// ======================================================================
__global__ __launch_bounds__(256) void gemm_nn(
    const float* __restrict__ A, int lda, long long sA,
    const float* __restrict__ B, int ldb, long long sB,
    float* __restrict__ C, int ldc, long long sC,
    int M, int N, int K, int klimit_flag)
{
    A += (long long)blockIdx.z * sA;
    B += (long long)blockIdx.z * sB;
    C += (long long)blockIdx.z * sC;

    __shared__ float As[16][128];
    __shared__ float Bs[16][128];

    const int tid = threadIdx.x;
    const int m0 = blockIdx.y * 128;
    const int n0 = blockIdx.x * 128;
    const int K_eff = klimit_flag ? min(K, ((int)blockIdx.y + 1) * 128) : K;

    const int lr = tid >> 1;
    const int lk = (tid & 1) << 3;
    const float* Ap = A + (long long)(m0 + lr) * lda + lk;
    const bool aok = (m0 + lr) < M;

    const int bkr = tid >> 4;
    const int bnc = (tid & 15) << 3;
    const float* Bp = B + (long long)bkr * ldb + n0 + bnc;
    const bool bok = (n0 + bnc) < N;

    const int tr = (tid >> 4) << 3;
    const int tc = (tid & 15) << 3;

    float acc[8][8];
#pragma unroll
    for (int i = 0; i < 8; i++)
#pragma unroll
        for (int j = 0; j < 8; j++) acc[i][j] = 0.f;

    for (int k0 = 0; k0 < K_eff; k0 += 16) {
        float4 a0 = make_float4(0.f,0.f,0.f,0.f), a1 = a0, b0 = a0, b1 = a0;
        if (aok) { a0 = *(const float4*)(Ap + k0); a1 = *(const float4*)(Ap + k0 + 4); }
        if (bok) {
            b0 = *(const float4*)(Bp + (long long)k0 * ldb);
            b1 = *(const float4*)(Bp + (long long)k0 * ldb + 4);
        }
        As[lk+0][lr]=a0.x; As[lk+1][lr]=a0.y; As[lk+2][lr]=a0.z; As[lk+3][lr]=a0.w;
        As[lk+4][lr]=a1.x; As[lk+5][lr]=a1.y; As[lk+6][lr]=a1.z; As[lk+7][lr]=a1.w;
        *(float4*)&Bs[bkr][bnc]     = b0;
        *(float4*)&Bs[bkr][bnc + 4] = b1;
        __syncthreads();

#pragma unroll
        for (int kk = 0; kk < 16; kk++) {
            float4 x0 = *(const float4*)&As[kk][tr];
            float4 x1 = *(const float4*)&As[kk][tr + 4];
            float4 y0 = *(const float4*)&Bs[kk][tc];
            float4 y1 = *(const float4*)&Bs[kk][tc + 4];
            float av_[8] = {x0.x,x0.y,x0.z,x0.w,x1.x,x1.y,x1.z,x1.w};
            float bv_[8] = {y0.x,y0.y,y0.z,y0.w,y1.x,y1.y,y1.z,y1.w};
#pragma unroll
            for (int i = 0; i < 8; i++)
#pragma unroll
                for (int j = 0; j < 8; j++)
                    acc[i][j] = fmaf(av_[i], bv_[j], acc[i][j]);
        }
        __syncthreads();
    }

#pragma unroll
    for (int i = 0; i < 8; i++) {
        const int r = m0 + tr + i;
        if (r >= M) continue;
        float* Crow = C + (long long)r * ldc;
#pragma unroll
        for (int jj = 0; jj < 2; jj++) {
            const int c = n0 + tc + jj * 4;
            if (c >= N) continue;
            float4 v;
            v.x = acc[i][jj*4+0]; v.y = acc[i][jj*4+1];
            v.z = acc[i][jj*4+2]; v.w = acc[i][jj*4+3];
            *(float4*)(Crow + c) = v;
        }
    }
}

// ======================================================================
// RNN: 8-CTA cluster per batch element (unchanged, passing)
// ======================================================================
__global__ void __cluster_dims__(8, 1, 1) __launch_bounds__(512, 1)
rnn_kernel(const int* __restrict__ batch,
           const float* __restrict__ embproj,
           const float* __restrict__ W_hh,
           const float* __restrict__ b_hh,
           float* __restrict__ z)
{
    __shared__ float hbuf[2][512];
    __shared__ float part[8][64];

    const int t    = threadIdx.x;
    const int rank = blockIdx.x & 7;
    const int b    = blockIdx.x >> 3;
    const int row  = t & 63;
    const int kg   = t >> 6;
    const int grow = rank * 64 + row;

    float w[64];
    {
        const float* wp = W_hh + (long long)grow * H_ + kg * 64;
#pragma unroll
        for (int j = 0; j < 16; j++) {
            float4 v = *(const float4*)(wp + 4 * j);
            w[4*j+0] = v.x; w[4*j+1] = v.y; w[4*j+2] = v.z; w[4*j+3] = v.w;
        }
    }

    float bh = 0.f, xt = 0.f;
    if (t < 64) bh = b_hh[rank * 64 + t];

    hbuf[0][t] = 0.f;

    if (t < 64) {
        int tok = batch[b * L_ + 0];
        xt = embproj[(long long)tok * H_ + rank * 64 + t];
    }
    __syncthreads();

    int p = 0;
    for (int step = 0; step < L_; ++step) {
        const float4* h4 = (const float4*)hbuf[p];
        float s = 0.f;
#pragma unroll
        for (int j = 0; j < 16; j++) {
            float4 hv = h4[kg * 16 + j];
            s = fmaf(w[4*j+0], hv.x, s);
            s = fmaf(w[4*j+1], hv.y, s);
            s = fmaf(w[4*j+2], hv.z, s);
            s = fmaf(w[4*j+3], hv.w, s);
        }
        part[kg][row] = s;

        float xtn = 0.f;
        if (t < 64 && step + 1 < L_) {
            int tk = batch[b * L_ + step + 1];
            xtn = embproj[(long long)tk * H_ + rank * 64 + t];
        }
        __syncthreads();

        if (t < 64) {
            float v = part[0][t] + part[1][t] + part[2][t] + part[3][t]
                    + part[4][t] + part[5][t] + part[6][t] + part[7][t];
            v = tanhf(xt + v + bh);
            z[((long long)(b * L_ + step)) * H_ + rank * 64 + t] = v;

            uint32_t la = (uint32_t)__cvta_generic_to_shared(&hbuf[p ^ 1][rank * 64 + t]);
#pragma unroll
            for (int r = 0; r < 8; r++) {
                uint32_t ra;
                asm volatile("mapa.shared::cluster.u32 %0, %1, %2;"
                             : "=r"(ra) : "r"(la), "r"(r));
                asm volatile("st.shared::cluster.f32 [%0], %1;"
                             :: "r"(ra), "f"(v) : "memory");
            }
        }
        asm volatile("barrier.cluster.arrive.aligned;" ::: "memory");
        asm volatile("barrier.cluster.wait.aligned;"   ::: "memory");
        xt = xtn;
        p ^= 1;
    }
}

// ======================================================================
// Row softmax (unchanged)
// ======================================================================
__global__ __launch_bounds__(256) void softmax_rows(float* __restrict__ P)
{
    const int i = blockIdx.x;
    const int b = blockIdx.y;
    float* row = P + (size_t)b * LL + (size_t)i * L_;
    const int len = i;
    const int tileEnd = ((i >> 7) + 1) << 7;
    const int tid = threadIdx.x;

    __shared__ float sm[8];
    __shared__ float bc[2];

    if (len > 0) {
        float m = -1e30f;
        for (int j = tid; j < len; j += 256) m = fmaxf(m, row[j]);
#pragma unroll
        for (int o = 16; o; o >>= 1) m = fmaxf(m, __shfl_xor_sync(~0u, m, o));
        if ((tid & 31) == 0) sm[tid >> 5] = m;
        __syncthreads();
        if (tid == 0) {
            float v = sm[0];
            for (int wgt = 1; wgt < 8; wgt++) v = fmaxf(v, sm[wgt]);
            bc[0] = v;
        }
        __syncthreads();
        m = bc[0];

        float s = 0.f;
        for (int j = tid; j < len; j += 256) s += expf(row[j] - m);
#pragma unroll
        for (int o = 16; o; o >>= 1) s += __shfl_xor_sync(~0u, s, o);
        if ((tid & 31) == 0) sm[tid >> 5] = s;
        __syncthreads();
        if (tid == 0) {
            float v = sm[0];
            for (int wgt = 1; wgt < 8; wgt++) v += sm[wgt];
            bc[1] = 1.f / v;
        }
        __syncthreads();
        const float inv = bc[1];

        for (int j = tid; j < len; j += 256) row[j] = expf(row[j] - m) * inv;
    }
    for (int j = len + tid; j < tileEnd; j += 256) row[j] = 0.f;
}

// ======================================================================
// av row 0 = mean of z (unchanged)
// ======================================================================
__global__ __launch_bounds__(512) void av0_mean(const float* __restrict__ z,
                                                float* __restrict__ av)
{
    const int b = blockIdx.x;
    const float4* zb = (const float4*)(z + (size_t)b * LH);
    const int tid = threadIdx.x;
    const int hc = tid & 127;
    const int jg = tid >> 7;

    float4 acc = make_float4(0.f, 0.f, 0.f, 0.f);
#pragma unroll 8
    for (int j = jg * 512; j < (jg + 1) * 512; j++) {
        float4 v = zb[(long long)j * 128 + hc];
        acc.x += v.x; acc.y += v.y; acc.z += v.z; acc.w += v.w;
    }
    __shared__ float4 part[4][128];
    part[jg][hc] = acc;
    __syncthreads();
    if (tid < 128) {
        float4 s = part[0][tid];
        float4 p1 = part[1][tid], p2 = part[2][tid], p3 = part[3][tid];
        s.x = (s.x + p1.x + p2.x + p3.x) * (1.f / L_);
        s.y = (s.y + p1.y + p2.y + p3.y) * (1.f / L_);
        s.z = (s.z + p1.z + p2.z + p3.z) * (1.f / L_);
        s.w = (s.w + p1.w + p2.w + p3.w) * (1.f / L_);
        ((float4*)(av + (size_t)b * LH))[tid] = s;
    }
}

// ======================================================================
// split fp32 -> (bf16 hi, bf16 lo)
// ======================================================================
__global__ __launch_bounds__(1024) void split_bf16(
    const float* __restrict__ x, __nv_bfloat16* __restrict__ hi,
    __nv_bfloat16* __restrict__ lo, int n)
{
    int i = blockIdx.x * 1024 + threadIdx.x;
    if (i < n) {
        float v = x[i];
        __nv_bfloat16 h = __float2bfloat16(v);
        hi[i] = h;
        lo[i] = __float2bfloat16(v - __bfloat162float(h));
    }
}

// ======================================================================
// HMMA bf16-split logit GEMM:
//   out[16384, 10000] = dec[16384,512] @ W_d[10000,512]^T + b_d
//   acc += Ahi*Bhi^T + Ahi*Blo^T + Alo*Bhi^T   (fp32 accumulate)
// Block 128x128, 8 warps (2x4), warp tile 64x32, K-chunk 32, double-buffered.
// smem rows padded to 40 bf16 (80 B) -> conflict-free ldmatrix.
// ======================================================================
#define LGM_STRIDE 40
#define LGM_ARR    (128 * LGM_STRIDE)            // 5120 elements per array
#define LGM_STAGE  (4 * LGM_ARR)                 // 20480 elements per stage
#define LGM_SMEM   (2 * LGM_STAGE * 2)           // 81920 bytes

__global__ __launch_bounds__(256, 1) void logit_mma(
    const __nv_bfloat16* __restrict__ Ahi, const __nv_bfloat16* __restrict__ Alo,
    const __nv_bfloat16* __restrict__ Bhi, const __nv_bfloat16* __restrict__ Blo,
    const float* __restrict__ bias, float* __restrict__ out)
{
    extern __shared__ __nv_bfloat16 sm[];
    const int tid  = threadIdx.x;
    const int wid  = tid >> 5;
    const int lane = tid & 31;
    const int m0 = blockIdx.y * 128;
    const int n0 = blockIdx.x * 128;
    const int wm = wid >> 2;          // 0..1  -> m offset wm*64
    const int wn = wid & 3;           // 0..3  -> n offset wn*32

    // ---- gmem staging geometry: thread -> (row = tid>>1, halfrow = tid&1) ----
    const int srow = tid >> 1;                 // 0..127
    const int scol = (tid & 1) * 16;           // 0 or 16 (bf16 elems)

    uint4 stag[8];
    auto load_regs = [&](int kc) {
        const long long kof = (long long)kc * 32 + scol;
        const long long arow = (long long)(m0 + srow) * H_ + kof;
        stag[0] = *(const uint4*)(Ahi + arow);
        stag[1] = *(const uint4*)(Ahi + arow + 8);
        stag[2] = *(const uint4*)(Alo + arow);
        stag[3] = *(const uint4*)(Alo + arow + 8);
        const int nrow = n0 + srow;
        if (nrow < V_) {
            const long long brow = (long long)nrow * H_ + kof;
            stag[4] = *(const uint4*)(Bhi + brow);
            stag[5] = *(const uint4*)(Bhi + brow + 8);
            stag[6] = *(const uint4*)(Blo + brow);
            stag[7] = *(const uint4*)(Blo + brow + 8);
        } else {
            uint4 zz = make_uint4(0, 0, 0, 0);
            stag[4] = zz; stag[5] = zz; stag[6] = zz; stag[7] = zz;
        }
    };
    auto store_smem = [&](int s) {
        __nv_bfloat16* st = sm + s * LGM_STAGE;
        const int off = srow * LGM_STRIDE + scol;
#pragma unroll
        for (int a = 0; a < 4; a++) {
            *(uint4*)(st + a * LGM_ARR + off)     = stag[2 * a];
            *(uint4*)(st + a * LGM_ARR + off + 8) = stag[2 * a + 1];
        }
    };

    // ---- ldmatrix per-lane invariants ----
    const uint32_t smem_base = smem_u32(sm);
    // A: lane&15 -> row, lane>>4 -> k-half
    const int a_row_off = (wm * 64 + (lane & 15)) * LGM_STRIDE + (lane >> 4) * 8;
    // B: lane&7 -> n-row, (lane>>3)&1 -> k-half (lanes 16-31 ignored by x2)
    const int b_row_off = (wn * 32 + (lane & 7)) * LGM_STRIDE + ((lane >> 3) & 1) * 8;

    float acc[4][4][4];
#pragma unroll
    for (int i = 0; i < 4; i++)
#pragma unroll
        for (int j = 0; j < 4; j++)
#pragma unroll
            for (int r = 0; r < 4; r++) acc[i][j][r] = 0.f;

    auto compute = [&](int s) {
        const uint32_t base = smem_base + s * LGM_STAGE * 2;
#pragma unroll
        for (int kk = 0; kk < 32; kk += 16) {
            uint32_t ah[4][4], al[4][4], bh[4][2], bl[4][2];
#pragma unroll
            for (int mt = 0; mt < 4; mt++) {
                const uint32_t aoff = base + (a_row_off + mt * 16 * LGM_STRIDE + kk) * 2;
                LDSM_X4(ah[mt][0], ah[mt][1], ah[mt][2], ah[mt][3], aoff);
                LDSM_X4(al[mt][0], al[mt][1], al[mt][2], al[mt][3], aoff + LGM_ARR * 2);
            }
#pragma unroll
            for (int nt = 0; nt < 4; nt++) {
                const uint32_t boff = base + (2 * LGM_ARR + b_row_off + nt * 8 * LGM_STRIDE + kk) * 2;
                LDSM_X2(bh[nt][0], bh[nt][1], boff);
                LDSM_X2(bl[nt][0], bl[nt][1], boff + LGM_ARR * 2);
            }
#pragma unroll
            for (int mt = 0; mt < 4; mt++)
#pragma unroll
                for (int nt = 0; nt < 4; nt++) {
                    MMA_BF16(acc[mt][nt], ah[mt], bh[nt]);
                    MMA_BF16(acc[mt][nt], ah[mt], bl[nt]);
                    MMA_BF16(acc[mt][nt], al[mt], bh[nt]);
                }
        }
    };

    // ---- mainloop: 16 chunks of K=32, double-buffered ----
    load_regs(0);
    store_smem(0);
    __syncthreads();

    for (int kc = 0; kc < 16; ++kc) {
        const int p = kc & 1;
        if (kc + 1 < 16) load_regs(kc + 1);
        compute(p);
        if (kc + 1 < 16) {
            __syncthreads();
            store_smem(p ^ 1);
            __syncthreads();
        }
    }

    // ---- epilogue ----
    const int g  = lane >> 2;          // row-in-8
    const int qc = (lane & 3) * 2;     // col pair
#pragma unroll
    for (int mt = 0; mt < 4; mt++) {
        const int r0 = m0 + wm * 64 + mt * 16 + g;
#pragma unroll
        for (int nt = 0; nt < 4; nt++) {
            const int c = n0 + wn * 32 + nt * 8 + qc;
            if (c >= V_) continue;
            const float bx = bias[c], by = bias[c + 1];
            float2 v0 = make_float2(acc[mt][nt][0] + bx, acc[mt][nt][1] + by);
            float2 v1 = make_float2(acc[mt][nt][2] + bx, acc[mt][nt][3] + by);
            *(float2*)(out + (long long)r0 * V_ + c) = v0;
            *(float2*)(out + (long long)(r0 + 8) * V_ + c) = v1;
        }
    }
}

// ======================================================================
extern "C" void kernel_launch(void* const* d_in, const int* in_sizes, int n_in,
                              void* d_out, int out_size)
{
    const int*   batch = (const int*)  d_in[0];
    const float* emb   = (const float*)d_in[1];
    const float* W_ih  = (const float*)d_in[2];
    const float* b_ih  = (const float*)d_in[3];
    const float* W_hh  = (const float*)d_in[4];
    const float* b_hh  = (const float*)d_in[5];
    const float* W_c   = (const float*)d_in[6];
    const float* b_c   = (const float*)d_in[7];
    const float* W_d   = (const float*)d_in[8];
    const float* b_d   = (const float*)d_in[9];
    float* out = (float*)d_out;

    float *embproj, *zbuf, *Pbuf, *avbuf, *decbuf;
    __nv_bfloat16 *dhi, *dlo, *whi, *wlo;
    cudaGetSymbolAddress((void**)&embproj, g_embproj);
    cudaGetSymbolAddress((void**)&zbuf,    g_z);
    cudaGetSymbolAddress((void**)&Pbuf,    g_P);
    cudaGetSymbolAddress((void**)&avbuf,   g_av);
    cudaGetSymbolAddress((void**)&decbuf,  g_dec);
    cudaGetSymbolAddress((void**)&dhi,     g_dec_hi);
    cudaGetSymbolAddress((void**)&dlo,     g_dec_lo);
    cudaGetSymbolAddress((void**)&whi,     g_wd_hi);
    cudaGetSymbolAddress((void**)&wlo,     g_wd_lo);

    cudaFuncSetAttribute(logit_mma, cudaFuncAttributeMaxDynamicSharedMemorySize, LGM_SMEM);

    // 1. embproj[V,H] = emb @ W_ih^T + b_ih
    gemm_nt<<<dim3(4, 79, 1), 256>>>(emb, H_, 0, W_ih, H_, 0,
                                     embproj, H_, 0,
                                     V_, H_, H_, b_ih, 0);

    // split W_d early (independent of everything else)
    split_bf16<<<(V_ * H_ + 1023) / 1024, 1024>>>(W_d, whi, wlo, V_ * H_);

    // 2. RNN scan -> z
    rnn_kernel<<<64, 512>>>(batch, embproj, W_hh, b_hh, zbuf);

    // 3. scores S = z @ z^T (causal tiles only)
    gemm_nt<<<dim3(16, 16, B_), 256>>>(zbuf, H_, LH, zbuf, H_, LH,
                                       Pbuf, L_, LL,
                                       L_, L_, H_, nullptr, 2);

    // 4. row softmax in place
    softmax_rows<<<dim3(L_, B_), 256>>>(Pbuf);

    // 5. av = P @ z  (K limited per row tile)
    gemm_nn<<<dim3(4, 16, B_), 256>>>(Pbuf, L_, LL, zbuf, H_, LH,
                                      avbuf, H_, LH,
                                      L_, H_, L_, 1);

    // 6. fix row 0: uniform attention over all positions
    av0_mean<<<B_, 512>>>(zbuf, avbuf);

    // 7. dec = av @ W_c[:, :H]^T + b_c ; dec += z @ W_c[:, H:]^T
    gemm_nt<<<dim3(4, 128, 1), 256>>>(avbuf, H_, 0, W_c, 2 * H_, 0,
                                      decbuf, H_, 0,
                                      B_ * L_, H_, H_, b_c, 0);
    gemm_nt<<<dim3(4, 128, 1), 256>>>(zbuf, H_, 0, W_c + H_, 2 * H_, 0,
                                      decbuf, H_, 0,
                                      B_ * L_, H_, H_, nullptr, 1);

    // 8. split dec -> bf16 hi/lo
    split_bf16<<<(B_ * L_ * H_ + 1023) / 1024, 1024>>>(decbuf, dhi, dlo, B_ * L_ * H_);

    // 9. logits = dec @ W_d^T + b_d  (HMMA bf16-split)
    logit_mma<<<dim3(79, 128, 1), 256, LGM_SMEM>>>(dhi, dlo, whi, wlo, b_d, out);
}

// round 8
// speedup vs baseline: 1.6572x; 1.6572x over previous
#include <cuda_runtime.h>
#include <cuda_bf16.h>
#include <cstdint>

#define B_ 8
#define L_ 2048
#define V_ 10000
#define H_ 512

static const long long LH = (long long)L_ * H_;       // 1048576
static const long long LL = (long long)L_ * L_;       // 4194304

// ---------------- static device scratch (no allocations) ----------------
__device__ float g_embproj[V_ * H_];                   // 20.5 MB
__device__ float g_z[B_ * L_ * H_];                    // 33.5 MB
__device__ float g_P[(size_t)B_ * L_ * L_];            // 134 MB
__device__ float g_av[B_ * L_ * H_];                   // 33.5 MB
__device__ float g_dec[B_ * L_ * H_];                  // 33.5 MB

__device__ __nv_bfloat16 g_dec_hi[B_ * L_ * H_];
__device__ __nv_bfloat16 g_dec_lo[B_ * L_ * H_];
__device__ __nv_bfloat16 g_wd_hi[V_ * H_];
__device__ __nv_bfloat16 g_wd_lo[V_ * H_];
__device__ __nv_bfloat16 g_z_hi[B_ * L_ * H_];
__device__ __nv_bfloat16 g_z_lo[B_ * L_ * H_];
__device__ __nv_bfloat16 g_av_hi[B_ * L_ * H_];
__device__ __nv_bfloat16 g_av_lo[B_ * L_ * H_];
__device__ __nv_bfloat16 g_emb_hi[V_ * H_];
__device__ __nv_bfloat16 g_emb_lo[V_ * H_];
__device__ __nv_bfloat16 g_wih_hi[H_ * H_];
__device__ __nv_bfloat16 g_wih_lo[H_ * H_];
__device__ __nv_bfloat16 g_wc_hi[H_ * 2 * H_];
__device__ __nv_bfloat16 g_wc_lo[H_ * 2 * H_];

__device__ __forceinline__ uint32_t smem_u32(const void* p) {
    uint32_t a;
    asm("{ .reg .u64 t; cvta.to.shared.u64 t, %1; cvt.u32.u64 %0, t; }"
        : "=r"(a) : "l"(p));
    return a;
}

#define LDSM_X4(r0, r1, r2, r3, addr)                                         \
    asm volatile("ldmatrix.sync.aligned.m8n8.x4.shared.b16 {%0,%1,%2,%3}, [%4];" \
                 : "=r"(r0), "=r"(r1), "=r"(r2), "=r"(r3) : "r"(addr))
#define LDSM_X2(r0, r1, addr)                                                 \
    asm volatile("ldmatrix.sync.aligned.m8n8.x2.shared.b16 {%0,%1}, [%2];"    \
                 : "=r"(r0), "=r"(r1) : "r"(addr))
#define MMA_BF16(c, a, b)                                                     \
    asm volatile("mma.sync.aligned.m16n8k16.row.col.f32.bf16.bf16.f32 "       \
                 "{%0,%1,%2,%3}, {%4,%5,%6,%7}, {%8,%9}, {%0,%1,%2,%3};"      \
                 : "+f"((c)[0]), "+f"((c)[1]), "+f"((c)[2]), "+f"((c)[3])     \
                 : "r"((a)[0]), "r"((a)[1]), "r"((a)[2]), "r"((a)[3]),        \
                   "r"((b)[0]), "r"((b)[1]))

__device__ __forceinline__ void cp16(uint32_t dst, const void* src, bool pred) {
    int sz = pred ? 16 : 0;
    asm volatile("cp.async.cg.shared.global [%0], [%1], 16, %2;"
                 :: "r"(dst), "l"(src), "r"(sz));
}
#define CP_COMMIT() asm volatile("cp.async.commit_group;" ::: "memory")
#define CP_WAIT1()  asm volatile("cp.async.wait_group 1;" ::: "memory")
#define CP_WAIT0()  asm volatile("cp.async.wait_group 0;" ::: "memory")

// ======================================================================
// Generic split-bf16 HMMA NT GEMM:
//   C[M,N] = (Ahi+Alo)[M,K] @ (Bhi+Blo)[N,K]^T (+bias) (+=C)
//   acc += Ahi*Bhi + Ahi*Blo + Alo*Bhi  (fp32 accumulate; lo*lo dropped)
// flags: bit0 = accumulate into C, bit1 = causal tile skip (skip bx > by)
// Block 128x128, 8 warps (2x4), warp tile 64x32, K-chunk 32,
// cp.async double-buffered. K % 32 == 0. smem rows stride 40 bf16.
// Each thread loads ONE row-half (32 bytes = 2 x cp16) per array per chunk.
// ======================================================================
#define HG_STRIDE 40
#define HG_ARR    (128 * HG_STRIDE)              // 5120 bf16 per array
#define HG_STAGE  (4 * HG_ARR)                   // per stage (Ahi,Alo,Bhi,Blo)
#define HG_SMEM   (2 * HG_STAGE * 2)             // 81920 bytes

__global__ __launch_bounds__(256, 1) void hgemm_nt(
    const __nv_bfloat16* __restrict__ Ahi, const __nv_bfloat16* __restrict__ Alo,
    int lda, long long sA,
    const __nv_bfloat16* __restrict__ Bhi, const __nv_bfloat16* __restrict__ Blo,
    int ldb, long long sB,
    float* __restrict__ C, int ldc, long long sC,
    int M, int N, int K,
    const float* __restrict__ bias, int flags)
{
    if ((flags & 2) && blockIdx.x > blockIdx.y) return;
    Ahi += (long long)blockIdx.z * sA;  Alo += (long long)blockIdx.z * sA;
    Bhi += (long long)blockIdx.z * sB;  Blo += (long long)blockIdx.z * sB;
    C   += (long long)blockIdx.z * sC;

    extern __shared__ __nv_bfloat16 sm[];
    const uint32_t smem_base = smem_u32(sm);
    const int tid  = threadIdx.x;
    const int wid  = tid >> 5;
    const int lane = tid & 31;
    const int m0 = blockIdx.y * 128;
    const int n0 = blockIdx.x * 128;
    const int wm = wid >> 2;                    // 0..1 -> m offset wm*64
    const int wn = wid & 3;                     // 0..3 -> n offset wn*32
    const int nk = K >> 5;                      // K chunks of 32

    // ---- cp.async geometry: thread -> (row r, half cc_) ----
    // Each chunk-row is 32 bf16 = 64 bytes; thread covers 32 bytes = 2 cp16.
    const int r   = (tid >> 1) & 127;
    const int cc_ = tid & 1;                    // element offset cc_*16
    const int rowA = m0 + r;
    const int rowB = n0 + r;
    const bool pA = rowA < M;
    const bool pB = rowB < N;
    const long long offA = (long long)(pA ? rowA : M - 1) * lda + cc_ * 16;
    const long long offB = (long long)(pB ? rowB : N - 1) * ldb + cc_ * 16;
    const uint32_t dstoff = (uint32_t)(r * HG_STRIDE + cc_ * 16) * 2;

    auto issue = [&](int kc, int s) {
        const uint32_t db = smem_base + (uint32_t)(s * HG_STAGE) * 2 + dstoff;
        const long long ko = (long long)kc * 32;
        cp16(db + 0 * HG_ARR * 2,      Ahi + offA + ko,     pA);
        cp16(db + 0 * HG_ARR * 2 + 16, Ahi + offA + ko + 8, pA);
        cp16(db + 1 * HG_ARR * 2,      Alo + offA + ko,     pA);
        cp16(db + 1 * HG_ARR * 2 + 16, Alo + offA + ko + 8, pA);
        cp16(db + 2 * HG_ARR * 2,      Bhi + offB + ko,     pB);
        cp16(db + 2 * HG_ARR * 2 + 16, Bhi + offB + ko + 8, pB);
        cp16(db + 3 * HG_ARR * 2,      Blo + offB + ko,     pB);
        cp16(db + 3 * HG_ARR * 2 + 16, Blo + offB + ko + 8, pB);
        CP_COMMIT();
    };

    // ---- ldmatrix per-lane invariants (verified mapping, R5) ----
    const int a_row_off = (wm * 64 + (lane & 15)) * HG_STRIDE + (lane >> 4) * 8;
    const int b_row_off = (wn * 32 + (lane & 7)) * HG_STRIDE + ((lane >> 3) & 1) * 8;

    float acc[4][4][4];
#pragma unroll
    for (int i = 0; i < 4; i++)
#pragma unroll
        for (int j = 0; j < 4; j++)
#pragma unroll
            for (int q = 0; q < 4; q++) acc[i][j][q] = 0.f;

    auto compute = [&](int s) {
        const uint32_t base = smem_base + (uint32_t)(s * HG_STAGE) * 2;
#pragma unroll
        for (int kk = 0; kk < 32; kk += 16) {
            uint32_t ah[4][4], al[4][4], bh[4][2], bl[4][2];
#pragma unroll
            for (int mt = 0; mt < 4; mt++) {
                const uint32_t aoff = base + (a_row_off + mt * 16 * HG_STRIDE + kk) * 2;
                LDSM_X4(ah[mt][0], ah[mt][1], ah[mt][2], ah[mt][3], aoff);
                LDSM_X4(al[mt][0], al[mt][1], al[mt][2], al[mt][3], aoff + HG_ARR * 2);
            }
#pragma unroll
            for (int nt = 0; nt < 4; nt++) {
                const uint32_t boff = base + (2 * HG_ARR + b_row_off + nt * 8 * HG_STRIDE + kk) * 2;
                LDSM_X2(bh[nt][0], bh[nt][1], boff);
                LDSM_X2(bl[nt][0], bl[nt][1], boff + HG_ARR * 2);
            }
#pragma unroll
            for (int mt = 0; mt < 4; mt++)
#pragma unroll
                for (int nt = 0; nt < 4; nt++) {
                    MMA_BF16(acc[mt][nt], ah[mt], bh[nt]);
                    MMA_BF16(acc[mt][nt], ah[mt], bl[nt]);
                    MMA_BF16(acc[mt][nt], al[mt], bh[nt]);
                }
        }
    };

    // ---- pipeline: 2 stages, cp.async overlapped ----
    // Invariant entering iteration kc: group kc is COMPLETE in smem.
    issue(0, 0);
    if (nk > 1) { issue(1, 1); CP_WAIT1(); }
    else        { CP_WAIT0(); }
    __syncthreads();

    for (int kc = 0; kc < nk; ++kc) {
        const int p = kc & 1;
        compute(p);
        __syncthreads();
        if (kc + 2 < nk) {
            issue(kc + 2, p);
            CP_WAIT1();          // group kc+1 complete; kc+2 may be pending
        } else {
            CP_WAIT0();          // tail: drain everything
        }
        __syncthreads();
    }

    // ---- epilogue ----
    const int g  = lane >> 2;
    const int qc = (lane & 3) * 2;
#pragma unroll
    for (int mt = 0; mt < 4; mt++) {
        const int r0 = m0 + wm * 64 + mt * 16 + g;
        if (r0 >= M) continue;
#pragma unroll
        for (int nt = 0; nt < 4; nt++) {
            const int c = n0 + wn * 32 + nt * 8 + qc;
            if (c >= N) continue;
            float bx = 0.f, by = 0.f;
            if (bias) { bx = bias[c]; by = bias[c + 1]; }
            float2 v0 = make_float2(acc[mt][nt][0] + bx, acc[mt][nt][1] + by);
            float2 v1 = make_float2(acc[mt][nt][2] + bx, acc[mt][nt][3] + by);
            float* p0 = C + (long long)r0 * ldc + c;
            float* p1 = C + (long long)(r0 + 8) * ldc + c;
            if (flags & 1) {
                float2 o0 = *(const float2*)p0;
                v0.x += o0.x; v0.y += o0.y;
                if (r0 + 8 < M) {
                    float2 o1 = *(const float2*)p1;
                    v1.x += o1.x; v1.y += o1.y;
                }
            }
            *(float2*)p0 = v0;
            if (r0 + 8 < M) *(float2*)p1 = v1;
        }
    }
}

// ======================================================================
// fp32 NN GEMM: C[M,N] = A[M,K] * B[K,N]   (klimit for causal P @ z)
// ======================================================================
__global__ __launch_bounds__(256) void gemm_nn(
    const float* __restrict__ A, int lda, long long sA,
    const float* __restrict__ B, int ldb, long long sB,
    float* __restrict__ C, int ldc, long long sC,
    int M, int N, int K, int klimit_flag)
{
    A += (long long)blockIdx.z * sA;
    B += (long long)blockIdx.z * sB;
    C += (long long)blockIdx.z * sC;

    __shared__ float As[16][128];
    __shared__ float Bs[16][128];

    const int tid = threadIdx.x;
    const int m0 = blockIdx.y * 128;
    const int n0 = blockIdx.x * 128;
    const int K_eff = klimit_flag ? min(K, ((int)blockIdx.y + 1) * 128) : K;

    const int lr = tid >> 1;
    const int lk = (tid & 1) << 3;
    const float* Ap = A + (long long)(m0 + lr) * lda + lk;
    const bool aok = (m0 + lr) < M;

    const int bkr = tid >> 4;
    const int bnc = (tid & 15) << 3;
    const float* Bp = B + (long long)bkr * ldb + n0 + bnc;
    const bool bok = (n0 + bnc) < N;

    const int tr = (tid >> 4) << 3;
    const int tc = (tid & 15) << 3;

    float acc[8][8];
#pragma unroll
    for (int i = 0; i < 8; i++)
#pragma unroll
        for (int j = 0; j < 8; j++) acc[i][j] = 0.f;

    for (int k0 = 0; k0 < K_eff; k0 += 16) {
        float4 a0 = make_float4(0.f,0.f,0.f,0.f), a1 = a0, b0 = a0, b1 = a0;
        if (aok) { a0 = *(const float4*)(Ap + k0); a1 = *(const float4*)(Ap + k0 + 4); }
        if (bok) {
            b0 = *(const float4*)(Bp + (long long)k0 * ldb);
            b1 = *(const float4*)(Bp + (long long)k0 * ldb + 4);
        }
        As[lk+0][lr]=a0.x; As[lk+1][lr]=a0.y; As[lk+2][lr]=a0.z; As[lk+3][lr]=a0.w;
        As[lk+4][lr]=a1.x; As[lk+5][lr]=a1.y; As[lk+6][lr]=a1.z; As[lk+7][lr]=a1.w;
        *(float4*)&Bs[bkr][bnc]     = b0;
        *(float4*)&Bs[bkr][bnc + 4] = b1;
        __syncthreads();

#pragma unroll
        for (int kk = 0; kk < 16; kk++) {
            float4 x0 = *(const float4*)&As[kk][tr];
            float4 x1 = *(const float4*)&As[kk][tr + 4];
            float4 y0 = *(const float4*)&Bs[kk][tc];
            float4 y1 = *(const float4*)&Bs[kk][tc + 4];
            float av_[8] = {x0.x,x0.y,x0.z,x0.w,x1.x,x1.y,x1.z,x1.w};
            float bv_[8] = {y0.x,y0.y,y0.z,y0.w,y1.x,y1.y,y1.z,y1.w};
#pragma unroll
            for (int i = 0; i < 8; i++)
#pragma unroll
                for (int j = 0; j < 8; j++)
                    acc[i][j] = fmaf(av_[i], bv_[j], acc[i][j]);
        }
        __syncthreads();
    }

#pragma unroll
    for (int i = 0; i < 8; i++) {
        const int rr = m0 + tr + i;
        if (rr >= M) continue;
        float* Crow = C + (long long)rr * ldc;
#pragma unroll
        for (int jj = 0; jj < 2; jj++) {
            const int c = n0 + tc + jj * 4;
            if (c >= N) continue;
            float4 v;
            v.x = acc[i][jj*4+0]; v.y = acc[i][jj*4+1];
            v.z = acc[i][jj*4+2]; v.w = acc[i][jj*4+3];
            *(float4*)(Crow + c) = v;
        }
    }
}

// ======================================================================
// RNN: 8-CTA cluster per batch element (unchanged, passing)
// ======================================================================
__global__ void __cluster_dims__(8, 1, 1) __launch_bounds__(512, 1)
rnn_kernel(const int* __restrict__ batch,
           const float* __restrict__ embproj,
           const float* __restrict__ W_hh,
           const float* __restrict__ b_hh,
           float* __restrict__ z)
{
    __shared__ float hbuf[2][512];
    __shared__ float part[8][64];

    const int t    = threadIdx.x;
    const int rank = blockIdx.x & 7;
    const int b    = blockIdx.x >> 3;
    const int row  = t & 63;
    const int kg   = t >> 6;
    const int grow = rank * 64 + row;

    float w[64];
    {
        const float* wp = W_hh + (long long)grow * H_ + kg * 64;
#pragma unroll
        for (int j = 0; j < 16; j++) {
            float4 v = *(const float4*)(wp + 4 * j);
            w[4*j+0] = v.x; w[4*j+1] = v.y; w[4*j+2] = v.z; w[4*j+3] = v.w;
        }
    }

    float bh = 0.f, xt = 0.f;
    if (t < 64) bh = b_hh[rank * 64 + t];

    hbuf[0][t] = 0.f;

    if (t < 64) {
        int tok = batch[b * L_ + 0];
        xt = embproj[(long long)tok * H_ + rank * 64 + t];
    }
    __syncthreads();

    int p = 0;
    for (int step = 0; step < L_; ++step) {
        const float4* h4 = (const float4*)hbuf[p];
        float s = 0.f;
#pragma unroll
        for (int j = 0; j < 16; j++) {
            float4 hv = h4[kg * 16 + j];
            s = fmaf(w[4*j+0], hv.x, s);
            s = fmaf(w[4*j+1], hv.y, s);
            s = fmaf(w[4*j+2], hv.z, s);
            s = fmaf(w[4*j+3], hv.w, s);
        }
        part[kg][row] = s;

        float xtn = 0.f;
        if (t < 64 && step + 1 < L_) {
            int tk = batch[b * L_ + step + 1];
            xtn = embproj[(long long)tk * H_ + rank * 64 + t];
        }
        __syncthreads();

        if (t < 64) {
            float v = part[0][t] + part[1][t] + part[2][t] + part[3][t]
                    + part[4][t] + part[5][t] + part[6][t] + part[7][t];
            v = tanhf(xt + v + bh);
            z[((long long)(b * L_ + step)) * H_ + rank * 64 + t] = v;

            uint32_t la = (uint32_t)__cvta_generic_to_shared(&hbuf[p ^ 1][rank * 64 + t]);
#pragma unroll
            for (int q = 0; q < 8; q++) {
                uint32_t ra;
                asm volatile("mapa.shared::cluster.u32 %0, %1, %2;"
                             : "=r"(ra) : "r"(la), "r"(q));
                asm volatile("st.shared::cluster.f32 [%0], %1;"
                             :: "r"(ra), "f"(v) : "memory");
            }
        }
        asm volatile("barrier.cluster.arrive.aligned;" ::: "memory");
        asm volatile("barrier.cluster.wait.aligned;"   ::: "memory");
        xt = xtn;
        p ^= 1;
    }
}

// ======================================================================
// Row softmax (unchanged)
// ======================================================================
__global__ __launch_bounds__(256) void softmax_rows(float* __restrict__ P)
{
    const int i = blockIdx.x;
    const int b = blockIdx.y;
    float* row = P + (size_t)b * LL + (size_t)i * L_;
    const int len = i;
    const int tileEnd = ((i >> 7) + 1) << 7;
    const int tid = threadIdx.x;

    __shared__ float sm_[8];
    __shared__ float bc[2];

    if (len > 0) {
        float m = -1e30f;
        for (int j = tid; j < len; j += 256) m = fmaxf(m, row[j]);
#pragma unroll
        for (int o = 16; o; o >>= 1) m = fmaxf(m, __shfl_xor_sync(~0u, m, o));
        if ((tid & 31) == 0) sm_[tid >> 5] = m;
        __syncthreads();
        if (tid == 0) {
            float v = sm_[0];
            for (int wgt = 1; wgt < 8; wgt++) v = fmaxf(v, sm_[wgt]);
            bc[0] = v;
        }
        __syncthreads();
        m = bc[0];

        float s = 0.f;
        for (int j = tid; j < len; j += 256) s += expf(row[j] - m);
#pragma unroll
        for (int o = 16; o; o >>= 1) s += __shfl_xor_sync(~0u, s, o);
        if ((tid & 31) == 0) sm_[tid >> 5] = s;
        __syncthreads();
        if (tid == 0) {
            float v = sm_[0];
            for (int wgt = 1; wgt < 8; wgt++) v += sm_[wgt];
            bc[1] = 1.f / v;
        }
        __syncthreads();
        const float inv = bc[1];

        for (int j = tid; j < len; j += 256) row[j] = expf(row[j] - m) * inv;
    }
    for (int j = len + tid; j < tileEnd; j += 256) row[j] = 0.f;
}

// ======================================================================
// av row 0 = mean of z (unchanged)
// ======================================================================
__global__ __launch_bounds__(512) void av0_mean(const float* __restrict__ z,
                                                float* __restrict__ av)
{
    const int b = blockIdx.x;
    const float4* zb = (const float4*)(z + (size_t)b * LH);
    const int tid = threadIdx.x;
    const int hc = tid & 127;
    const int jg = tid >> 7;

    float4 acc = make_float4(0.f, 0.f, 0.f, 0.f);
#pragma unroll 8
    for (int j = jg * 512; j < (jg + 1) * 512; j++) {
        float4 v = zb[(long long)j * 128 + hc];
        acc.x += v.x; acc.y += v.y; acc.z += v.z; acc.w += v.w;
    }
    __shared__ float4 part[4][128];
    part[jg][hc] = acc;
    __syncthreads();
    if (tid < 128) {
        float4 s = part[0][tid];
        float4 p1 = part[1][tid], p2 = part[2][tid], p3 = part[3][tid];
        s.x = (s.x + p1.x + p2.x + p3.x) * (1.f / L_);
        s.y = (s.y + p1.y + p2.y + p3.y) * (1.f / L_);
        s.z = (s.z + p1.z + p2.z + p3.z) * (1.f / L_);
        s.w = (s.w + p1.w + p2.w + p3.w) * (1.f / L_);
        ((float4*)(av + (size_t)b * LH))[tid] = s;
    }
}

// ======================================================================
// split fp32 -> (bf16 hi, bf16 lo)
// ======================================================================
__global__ __launch_bounds__(1024) void split_bf16(
    const float* __restrict__ x, __nv_bfloat16* __restrict__ hi,
    __nv_bfloat16* __restrict__ lo, int n)
{
    int i = blockIdx.x * 1024 + threadIdx.x;
    if (i < n) {
        float v = x[i];
        __nv_bfloat16 h = __float2bfloat16(v);
        hi[i] = h;
        lo[i] = __float2bfloat16(v - __bfloat162float(h));
    }
}

// ======================================================================
extern "C" void kernel_launch(void* const* d_in, const int* in_sizes, int n_in,
                              void* d_out, int out_size)
{
    const int*   batch = (const int*)  d_in[0];
    const float* emb   = (const float*)d_in[1];
    const float* W_ih  = (const float*)d_in[2];
    const float* b_ih  = (const float*)d_in[3];
    const float* W_hh  = (const float*)d_in[4];
    const float* b_hh  = (const float*)d_in[5];
    const float* W_c   = (const float*)d_in[6];
    const float* b_c   = (const float*)d_in[7];
    const float* W_d   = (const float*)d_in[8];
    const float* b_d   = (const float*)d_in[9];
    float* out = (float*)d_out;

    float *embproj, *zbuf, *Pbuf, *avbuf, *decbuf;
    __nv_bfloat16 *dhi, *dlo, *wdhi, *wdlo, *zhi, *zlo, *avhi, *avlo;
    __nv_bfloat16 *ehi, *elo, *wihhi, *wihlo, *wchi, *wclo;
    cudaGetSymbolAddress((void**)&embproj, g_embproj);
    cudaGetSymbolAddress((void**)&zbuf,    g_z);
    cudaGetSymbolAddress((void**)&Pbuf,    g_P);
    cudaGetSymbolAddress((void**)&avbuf,   g_av);
    cudaGetSymbolAddress((void**)&decbuf,  g_dec);
    cudaGetSymbolAddress((void**)&dhi,     g_dec_hi);
    cudaGetSymbolAddress((void**)&dlo,     g_dec_lo);
    cudaGetSymbolAddress((void**)&wdhi,    g_wd_hi);
    cudaGetSymbolAddress((void**)&wdlo,    g_wd_lo);
    cudaGetSymbolAddress((void**)&zhi,     g_z_hi);
    cudaGetSymbolAddress((void**)&zlo,     g_z_lo);
    cudaGetSymbolAddress((void**)&avhi,    g_av_hi);
    cudaGetSymbolAddress((void**)&avlo,    g_av_lo);
    cudaGetSymbolAddress((void**)&ehi,     g_emb_hi);
    cudaGetSymbolAddress((void**)&elo,     g_emb_lo);
    cudaGetSymbolAddress((void**)&wihhi,   g_wih_hi);
    cudaGetSymbolAddress((void**)&wihlo,   g_wih_lo);
    cudaGetSymbolAddress((void**)&wchi,    g_wc_hi);
    cudaGetSymbolAddress((void**)&wclo,    g_wc_lo);

    cudaFuncSetAttribute(hgemm_nt, cudaFuncAttributeMaxDynamicSharedMemorySize, HG_SMEM);

    const int ML = B_ * L_;   // 16384

    // 0. splits of inputs
    split_bf16<<<(V_ * H_ + 1023) / 1024, 1024>>>(emb, ehi, elo, V_ * H_);
    split_bf16<<<(H_ * H_ + 1023) / 1024, 1024>>>(W_ih, wihhi, wihlo, H_ * H_);
    split_bf16<<<(H_ * 2 * H_ + 1023) / 1024, 1024>>>(W_c, wchi, wclo, H_ * 2 * H_);
    split_bf16<<<(V_ * H_ + 1023) / 1024, 1024>>>(W_d, wdhi, wdlo, V_ * H_);

    // 1. embproj[V,H] = emb @ W_ih^T + b_ih  (HMMA split)
    hgemm_nt<<<dim3(4, 79, 1), 256, HG_SMEM>>>(
        ehi, elo, H_, 0, wihhi, wihlo, H_, 0,
        embproj, H_, 0, V_, H_, H_, b_ih, 0);

    // 2. RNN scan -> z
    rnn_kernel<<<64, 512>>>(batch, embproj, W_hh, b_hh, zbuf);

    // 3. split z
    split_bf16<<<(ML * H_ + 1023) / 1024, 1024>>>(zbuf, zhi, zlo, ML * H_);

    // 4. scores S = z @ z^T (causal tiles only, HMMA split)
    hgemm_nt<<<dim3(16, 16, B_), 256, HG_SMEM>>>(
        zhi, zlo, H_, LH, zhi, zlo, H_, LH,
        Pbuf, L_, LL, L_, L_, H_, nullptr, 2);

    // 5. row softmax in place
    softmax_rows<<<dim3(L_, B_), 256>>>(Pbuf);

    // 6. av = P @ z  (fp32, K limited per row tile)
    gemm_nn<<<dim3(4, 16, B_), 256>>>(Pbuf, L_, LL, zbuf, H_, LH,
                                      avbuf, H_, LH,
                                      L_, H_, L_, 1);

    // 7. fix row 0: uniform attention over all positions
    av0_mean<<<B_, 512>>>(zbuf, avbuf);

    // 8. split av
    split_bf16<<<(ML * H_ + 1023) / 1024, 1024>>>(avbuf, avhi, avlo, ML * H_);

    // 9. dec = av @ W_c[:, :H]^T + b_c ; dec += z @ W_c[:, H:]^T  (HMMA split)
    hgemm_nt<<<dim3(4, 128, 1), 256, HG_SMEM>>>(
        avhi, avlo, H_, 0, wchi, wclo, 2 * H_, 0,
        decbuf, H_, 0, ML, H_, H_, b_c, 0);
    hgemm_nt<<<dim3(4, 128, 1), 256, HG_SMEM>>>(
        zhi, zlo, H_, 0, wchi + H_, wclo + H_, 2 * H_, 0,
        decbuf, H_, 0, ML, H_, H_, nullptr, 1);

    // 10. split dec
    split_bf16<<<(ML * H_ + 1023) / 1024, 1024>>>(decbuf, dhi, dlo, ML * H_);

    // 11. logits = dec @ W_d^T + b_d  (HMMA split)
    hgemm_nt<<<dim3(79, 128, 1), 256, HG_SMEM>>>(
        dhi, dlo, H_, 0, wdhi, wdlo, H_, 0,
        out, V_, 0, ML, V_, H_, b_d, 0);
}

// round 9
// speedup vs baseline: 1.7060x; 1.0295x over previous
#include <cuda_runtime.h>
#include <cuda_bf16.h>
#include <cstdint>

#define B_ 8
#define L_ 2048
#define V_ 10000
#define H_ 512

static const long long LH = (long long)L_ * H_;       // 1048576
static const long long LL = (long long)L_ * L_;       // 4194304

// ---------------- static device scratch (no allocations) ----------------
__device__ float g_embproj[V_ * H_];                   // 20.5 MB
__device__ float g_z[B_ * L_ * H_];                    // 33.5 MB
__device__ float g_P[(size_t)B_ * L_ * L_];            // 134 MB (raw scores)
__device__ float g_av[B_ * L_ * H_];                   // 33.5 MB
__device__ float g_dec[B_ * L_ * H_];                  // 33.5 MB

__device__ __nv_bfloat16 g_P_hi[(size_t)B_ * L_ * L_]; // 67 MB (probs hi)
__device__ __nv_bfloat16 g_P_lo[(size_t)B_ * L_ * L_]; // 67 MB (probs lo)
__device__ __nv_bfloat16 g_zT_hi[B_ * H_ * L_];        // 16.8 MB (z^T)
__device__ __nv_bfloat16 g_zT_lo[B_ * H_ * L_];
__device__ __nv_bfloat16 g_dec_hi[B_ * L_ * H_];
__device__ __nv_bfloat16 g_dec_lo[B_ * L_ * H_];
__device__ __nv_bfloat16 g_wd_hi[V_ * H_];
__device__ __nv_bfloat16 g_wd_lo[V_ * H_];
__device__ __nv_bfloat16 g_z_hi[B_ * L_ * H_];
__device__ __nv_bfloat16 g_z_lo[B_ * L_ * H_];
__device__ __nv_bfloat16 g_av_hi[B_ * L_ * H_];
__device__ __nv_bfloat16 g_av_lo[B_ * L_ * H_];
__device__ __nv_bfloat16 g_emb_hi[V_ * H_];
__device__ __nv_bfloat16 g_emb_lo[V_ * H_];
__device__ __nv_bfloat16 g_wih_hi[H_ * H_];
__device__ __nv_bfloat16 g_wih_lo[H_ * H_];
__device__ __nv_bfloat16 g_wc_hi[H_ * 2 * H_];
__device__ __nv_bfloat16 g_wc_lo[H_ * 2 * H_];

__device__ __forceinline__ uint32_t smem_u32(const void* p) {
    uint32_t a;
    asm("{ .reg .u64 t; cvta.to.shared.u64 t, %1; cvt.u32.u64 %0, t; }"
        : "=r"(a) : "l"(p));
    return a;
}

#define LDSM_X4(r0, r1, r2, r3, addr)                                         \
    asm volatile("ldmatrix.sync.aligned.m8n8.x4.shared.b16 {%0,%1,%2,%3}, [%4];" \
                 : "=r"(r0), "=r"(r1), "=r"(r2), "=r"(r3) : "r"(addr))
#define LDSM_X2(r0, r1, addr)                                                 \
    asm volatile("ldmatrix.sync.aligned.m8n8.x2.shared.b16 {%0,%1}, [%2];"    \
                 : "=r"(r0), "=r"(r1) : "r"(addr))
#define MMA_BF16(c, a, b)                                                     \
    asm volatile("mma.sync.aligned.m16n8k16.row.col.f32.bf16.bf16.f32 "       \
                 "{%0,%1,%2,%3}, {%4,%5,%6,%7}, {%8,%9}, {%0,%1,%2,%3};"      \
                 : "+f"((c)[0]), "+f"((c)[1]), "+f"((c)[2]), "+f"((c)[3])     \
                 : "r"((a)[0]), "r"((a)[1]), "r"((a)[2]), "r"((a)[3]),        \
                   "r"((b)[0]), "r"((b)[1]))

__device__ __forceinline__ void cp16(uint32_t dst, const void* src, bool pred) {
    int sz = pred ? 16 : 0;
    asm volatile("cp.async.cg.shared.global [%0], [%1], 16, %2;"
                 :: "r"(dst), "l"(src), "r"(sz));
}
#define CP_COMMIT() asm volatile("cp.async.commit_group;" ::: "memory")
#define CP_WAIT1()  asm volatile("cp.async.wait_group 1;" ::: "memory")
#define CP_WAIT0()  asm volatile("cp.async.wait_group 0;" ::: "memory")

// ======================================================================
// Generic split-bf16 HMMA NT GEMM:
//   C[M,N] = (Ahi+Alo)[M,K] @ (Bhi+Blo)[N,K]^T (+bias) (+=C)
// flags: bit0 = accumulate, bit1 = causal tile skip (skip bx > by),
//        bit2 = causal K-limit (K_eff = min(K, (by+1)*128))
// Block 128x128, 8 warps (2x4), warp tile 64x32, K-chunk 32,
// cp.async double-buffered. K % 32 == 0. smem rows stride 40 bf16.
// ======================================================================
#define HG_STRIDE 40
#define HG_ARR    (128 * HG_STRIDE)              // 5120 bf16 per array
#define HG_STAGE  (4 * HG_ARR)                   // per stage (Ahi,Alo,Bhi,Blo)
#define HG_SMEM   (2 * HG_STAGE * 2)             // 81920 bytes

__global__ __launch_bounds__(256, 1) void hgemm_nt(
    const __nv_bfloat16* __restrict__ Ahi, const __nv_bfloat16* __restrict__ Alo,
    int lda, long long sA,
    const __nv_bfloat16* __restrict__ Bhi, const __nv_bfloat16* __restrict__ Blo,
    int ldb, long long sB,
    float* __restrict__ C, int ldc, long long sC,
    int M, int N, int K,
    const float* __restrict__ bias, int flags)
{
    if ((flags & 2) && blockIdx.x > blockIdx.y) return;
    Ahi += (long long)blockIdx.z * sA;  Alo += (long long)blockIdx.z * sA;
    Bhi += (long long)blockIdx.z * sB;  Blo += (long long)blockIdx.z * sB;
    C   += (long long)blockIdx.z * sC;

    extern __shared__ __nv_bfloat16 sm[];
    const uint32_t smem_base = smem_u32(sm);
    const int tid  = threadIdx.x;
    const int wid  = tid >> 5;
    const int lane = tid & 31;
    const int m0 = blockIdx.y * 128;
    const int n0 = blockIdx.x * 128;
    const int wm = wid >> 2;                    // 0..1 -> m offset wm*64
    const int wn = wid & 3;                     // 0..3 -> n offset wn*32
    const int K_eff = (flags & 4) ? min(K, ((int)blockIdx.y + 1) * 128) : K;
    const int nk = K_eff >> 5;                  // K chunks of 32

    // ---- cp.async geometry: thread -> (row r, half cc_) ----
    const int r   = (tid >> 1) & 127;
    const int cc_ = tid & 1;                    // element offset cc_*16
    const int rowA = m0 + r;
    const int rowB = n0 + r;
    const bool pA = rowA < M;
    const bool pB = rowB < N;
    const long long offA = (long long)(pA ? rowA : M - 1) * lda + cc_ * 16;
    const long long offB = (long long)(pB ? rowB : N - 1) * ldb + cc_ * 16;
    const uint32_t dstoff = (uint32_t)(r * HG_STRIDE + cc_ * 16) * 2;

    auto issue = [&](int kc, int s) {
        const uint32_t db = smem_base + (uint32_t)(s * HG_STAGE) * 2 + dstoff;
        const long long ko = (long long)kc * 32;
        cp16(db + 0 * HG_ARR * 2,      Ahi + offA + ko,     pA);
        cp16(db + 0 * HG_ARR * 2 + 16, Ahi + offA + ko + 8, pA);
        cp16(db + 1 * HG_ARR * 2,      Alo + offA + ko,     pA);
        cp16(db + 1 * HG_ARR * 2 + 16, Alo + offA + ko + 8, pA);
        cp16(db + 2 * HG_ARR * 2,      Bhi + offB + ko,     pB);
        cp16(db + 2 * HG_ARR * 2 + 16, Bhi + offB + ko + 8, pB);
        cp16(db + 3 * HG_ARR * 2,      Blo + offB + ko,     pB);
        cp16(db + 3 * HG_ARR * 2 + 16, Blo + offB + ko + 8, pB);
        CP_COMMIT();
    };

    // ---- ldmatrix per-lane invariants (verified mapping) ----
    const int a_row_off = (wm * 64 + (lane & 15)) * HG_STRIDE + (lane >> 4) * 8;
    const int b_row_off = (wn * 32 + (lane & 7)) * HG_STRIDE + ((lane >> 3) & 1) * 8;

    float acc[4][4][4];
#pragma unroll
    for (int i = 0; i < 4; i++)
#pragma unroll
        for (int j = 0; j < 4; j++)
#pragma unroll
            for (int q = 0; q < 4; q++) acc[i][j][q] = 0.f;

    auto compute = [&](int s) {
        const uint32_t base = smem_base + (uint32_t)(s * HG_STAGE) * 2;
#pragma unroll
        for (int kk = 0; kk < 32; kk += 16) {
            uint32_t ah[4][4], al[4][4], bh[4][2], bl[4][2];
#pragma unroll
            for (int mt = 0; mt < 4; mt++) {
                const uint32_t aoff = base + (a_row_off + mt * 16 * HG_STRIDE + kk) * 2;
                LDSM_X4(ah[mt][0], ah[mt][1], ah[mt][2], ah[mt][3], aoff);
                LDSM_X4(al[mt][0], al[mt][1], al[mt][2], al[mt][3], aoff + HG_ARR * 2);
            }
#pragma unroll
            for (int nt = 0; nt < 4; nt++) {
                const uint32_t boff = base + (2 * HG_ARR + b_row_off + nt * 8 * HG_STRIDE + kk) * 2;
                LDSM_X2(bh[nt][0], bh[nt][1], boff);
                LDSM_X2(bl[nt][0], bl[nt][1], boff + HG_ARR * 2);
            }
#pragma unroll
            for (int mt = 0; mt < 4; mt++)
#pragma unroll
                for (int nt = 0; nt < 4; nt++) {
                    MMA_BF16(acc[mt][nt], ah[mt], bh[nt]);
                    MMA_BF16(acc[mt][nt], ah[mt], bl[nt]);
                    MMA_BF16(acc[mt][nt], al[mt], bh[nt]);
                }
        }
    };

    // ---- pipeline: 2 stages, cp.async overlapped ----
    issue(0, 0);
    if (nk > 1) { issue(1, 1); CP_WAIT1(); }
    else        { CP_WAIT0(); }
    __syncthreads();

    for (int kc = 0; kc < nk; ++kc) {
        const int p = kc & 1;
        compute(p);
        __syncthreads();
        if (kc + 2 < nk) {
            issue(kc + 2, p);
            CP_WAIT1();
        } else {
            CP_WAIT0();
        }
        __syncthreads();
    }

    // ---- epilogue ----
    const int g  = lane >> 2;
    const int qc = (lane & 3) * 2;
#pragma unroll
    for (int mt = 0; mt < 4; mt++) {
        const int r0 = m0 + wm * 64 + mt * 16 + g;
        if (r0 >= M) continue;
#pragma unroll
        for (int nt = 0; nt < 4; nt++) {
            const int c = n0 + wn * 32 + nt * 8 + qc;
            if (c >= N) continue;
            float bx = 0.f, by = 0.f;
            if (bias) { bx = bias[c]; by = bias[c + 1]; }
            float2 v0 = make_float2(acc[mt][nt][0] + bx, acc[mt][nt][1] + by);
            float2 v1 = make_float2(acc[mt][nt][2] + bx, acc[mt][nt][3] + by);
            float* p0 = C + (long long)r0 * ldc + c;
            float* p1 = C + (long long)(r0 + 8) * ldc + c;
            if (flags & 1) {
                float2 o0 = *(const float2*)p0;
                v0.x += o0.x; v0.y += o0.y;
                if (r0 + 8 < M) {
                    float2 o1 = *(const float2*)p1;
                    v1.x += o1.x; v1.y += o1.y;
                }
            }
            *(float2*)p0 = v0;
            if (r0 + 8 < M) *(float2*)p1 = v1;
        }
    }
}

// ======================================================================
// RNN: 8-CTA cluster per batch element; also emits z bf16 hi/lo (fused split)
// ======================================================================
__global__ void __cluster_dims__(8, 1, 1) __launch_bounds__(512, 1)
rnn_kernel(const int* __restrict__ batch,
           const float* __restrict__ embproj,
           const float* __restrict__ W_hh,
           const float* __restrict__ b_hh,
           float* __restrict__ z,
           __nv_bfloat16* __restrict__ zhi,
           __nv_bfloat16* __restrict__ zlo)
{
    __shared__ float hbuf[2][512];
    __shared__ float part[8][64];

    const int t    = threadIdx.x;
    const int rank = blockIdx.x & 7;
    const int b    = blockIdx.x >> 3;
    const int row  = t & 63;
    const int kg   = t >> 6;
    const int grow = rank * 64 + row;

    float w[64];
    {
        const float* wp = W_hh + (long long)grow * H_ + kg * 64;
#pragma unroll
        for (int j = 0; j < 16; j++) {
            float4 v = *(const float4*)(wp + 4 * j);
            w[4*j+0] = v.x; w[4*j+1] = v.y; w[4*j+2] = v.z; w[4*j+3] = v.w;
        }
    }

    float bh = 0.f, xt = 0.f;
    if (t < 64) bh = b_hh[rank * 64 + t];

    hbuf[0][t] = 0.f;

    if (t < 64) {
        int tok = batch[b * L_ + 0];
        xt = embproj[(long long)tok * H_ + rank * 64 + t];
    }
    __syncthreads();

    int p = 0;
    for (int step = 0; step < L_; ++step) {
        const float4* h4 = (const float4*)hbuf[p];
        float s = 0.f;
#pragma unroll
        for (int j = 0; j < 16; j++) {
            float4 hv = h4[kg * 16 + j];
            s = fmaf(w[4*j+0], hv.x, s);
            s = fmaf(w[4*j+1], hv.y, s);
            s = fmaf(w[4*j+2], hv.z, s);
            s = fmaf(w[4*j+3], hv.w, s);
        }
        part[kg][row] = s;

        float xtn = 0.f;
        if (t < 64 && step + 1 < L_) {
            int tk = batch[b * L_ + step + 1];
            xtn = embproj[(long long)tk * H_ + rank * 64 + t];
        }
        __syncthreads();

        if (t < 64) {
            float v = part[0][t] + part[1][t] + part[2][t] + part[3][t]
                    + part[4][t] + part[5][t] + part[6][t] + part[7][t];
            v = tanhf(xt + v + bh);
            const long long zo = ((long long)(b * L_ + step)) * H_ + rank * 64 + t;
            z[zo] = v;
            __nv_bfloat16 vh = __float2bfloat16(v);
            zhi[zo] = vh;
            zlo[zo] = __float2bfloat16(v - __bfloat162float(vh));

            uint32_t la = (uint32_t)__cvta_generic_to_shared(&hbuf[p ^ 1][rank * 64 + t]);
#pragma unroll
            for (int q = 0; q < 8; q++) {
                uint32_t ra;
                asm volatile("mapa.shared::cluster.u32 %0, %1, %2;"
                             : "=r"(ra) : "r"(la), "r"(q));
                asm volatile("st.shared::cluster.f32 [%0], %1;"
                             :: "r"(ra), "f"(v) : "memory");
            }
        }
        asm volatile("barrier.cluster.arrive.aligned;" ::: "memory");
        asm volatile("barrier.cluster.wait.aligned;"   ::: "memory");
        xt = xtn;
        p ^= 1;
    }
}

// ======================================================================
// Row softmax: read fp32 scores from S, write probs as bf16 hi/lo.
// Zeros written for j in [len, diag tile end) keep the K-limited
// P@z HMMA GEMM exact. Row 0 -> all zeros (fixed by av0_mean).
// ======================================================================
__global__ __launch_bounds__(256) void softmax_rows(
    const float* __restrict__ S,
    __nv_bfloat16* __restrict__ Phi, __nv_bfloat16* __restrict__ Plo)
{
    const int i = blockIdx.x;
    const int b = blockIdx.y;
    const float* row = S + (size_t)b * LL + (size_t)i * L_;
    __nv_bfloat16* rh = Phi + (size_t)b * LL + (size_t)i * L_;
    __nv_bfloat16* rl = Plo + (size_t)b * LL + (size_t)i * L_;
    const int len = i;
    const int tileEnd = ((i >> 7) + 1) << 7;
    const int tid = threadIdx.x;

    __shared__ float sm_[8];
    __shared__ float bc[2];

    if (len > 0) {
        float m = -1e30f;
        for (int j = tid; j < len; j += 256) m = fmaxf(m, row[j]);
#pragma unroll
        for (int o = 16; o; o >>= 1) m = fmaxf(m, __shfl_xor_sync(~0u, m, o));
        if ((tid & 31) == 0) sm_[tid >> 5] = m;
        __syncthreads();
        if (tid == 0) {
            float v = sm_[0];
            for (int wgt = 1; wgt < 8; wgt++) v = fmaxf(v, sm_[wgt]);
            bc[0] = v;
        }
        __syncthreads();
        m = bc[0];

        float s = 0.f;
        for (int j = tid; j < len; j += 256) s += expf(row[j] - m);
#pragma unroll
        for (int o = 16; o; o >>= 1) s += __shfl_xor_sync(~0u, s, o);
        if ((tid & 31) == 0) sm_[tid >> 5] = s;
        __syncthreads();
        if (tid == 0) {
            float v = sm_[0];
            for (int wgt = 1; wgt < 8; wgt++) v += sm_[wgt];
            bc[1] = 1.f / v;
        }
        __syncthreads();
        const float inv = bc[1];

        for (int j = tid; j < len; j += 256) {
            float pv = expf(row[j] - m) * inv;
            __nv_bfloat16 h = __float2bfloat16(pv);
            rh[j] = h;
            rl[j] = __float2bfloat16(pv - __bfloat162float(h));
        }
    }
    const __nv_bfloat16 zz = __float2bfloat16(0.f);
    for (int j = len + tid; j < tileEnd; j += 256) { rh[j] = zz; rl[j] = zz; }
}

// ======================================================================
// z [B,L,H] fp32 -> z^T [B,H,L] bf16 hi/lo (32x32 smem tiles)
// ======================================================================
__global__ __launch_bounds__(256) void transpose_split(
    const float* __restrict__ z,
    __nv_bfloat16* __restrict__ Thi, __nv_bfloat16* __restrict__ Tlo)
{
    __shared__ float tile[32][33];
    const int b  = blockIdx.z;
    const int l0 = blockIdx.x * 32;
    const int h0 = blockIdx.y * 32;
    const int tx = threadIdx.x & 31;
    const int ty = threadIdx.x >> 5;      // 0..7

    const float* zb = z + (size_t)b * LH;
#pragma unroll
    for (int i = ty; i < 32; i += 8)
        tile[i][tx] = zb[(long long)(l0 + i) * H_ + h0 + tx];
    __syncthreads();

    __nv_bfloat16* th = Thi + (size_t)b * H_ * L_;
    __nv_bfloat16* tl = Tlo + (size_t)b * H_ * L_;
#pragma unroll
    for (int i = ty; i < 32; i += 8) {
        float v = tile[tx][i];
        __nv_bfloat16 h = __float2bfloat16(v);
        const long long o = (long long)(h0 + i) * L_ + l0 + tx;
        th[o] = h;
        tl[o] = __float2bfloat16(v - __bfloat162float(h));
    }
}

// ======================================================================
// av row 0 = mean of z (unchanged)
// ======================================================================
__global__ __launch_bounds__(512) void av0_mean(const float* __restrict__ z,
                                                float* __restrict__ av)
{
    const int b = blockIdx.x;
    const float4* zb = (const float4*)(z + (size_t)b * LH);
    const int tid = threadIdx.x;
    const int hc = tid & 127;
    const int jg = tid >> 7;

    float4 acc = make_float4(0.f, 0.f, 0.f, 0.f);
#pragma unroll 8
    for (int j = jg * 512; j < (jg + 1) * 512; j++) {
        float4 v = zb[(long long)j * 128 + hc];
        acc.x += v.x; acc.y += v.y; acc.z += v.z; acc.w += v.w;
    }
    __shared__ float4 part[4][128];
    part[jg][hc] = acc;
    __syncthreads();
    if (tid < 128) {
        float4 s = part[0][tid];
        float4 p1 = part[1][tid], p2 = part[2][tid], p3 = part[3][tid];
        s.x = (s.x + p1.x + p2.x + p3.x) * (1.f / L_);
        s.y = (s.y + p1.y + p2.y + p3.y) * (1.f / L_);
        s.z = (s.z + p1.z + p2.z + p3.z) * (1.f / L_);
        s.w = (s.w + p1.w + p2.w + p3.w) * (1.f / L_);
        ((float4*)(av + (size_t)b * LH))[tid] = s;
    }
}

// ======================================================================
// split fp32 -> (bf16 hi, bf16 lo)
// ======================================================================
__global__ __launch_bounds__(1024) void split_bf16(
    const float* __restrict__ x, __nv_bfloat16* __restrict__ hi,
    __nv_bfloat16* __restrict__ lo, int n)
{
    int i = blockIdx.x * 1024 + threadIdx.x;
    if (i < n) {
        float v = x[i];
        __nv_bfloat16 h = __float2bfloat16(v);
        hi[i] = h;
        lo[i] = __float2bfloat16(v - __bfloat162float(h));
    }
}

// ======================================================================
extern "C" void kernel_launch(void* const* d_in, const int* in_sizes, int n_in,
                              void* d_out, int out_size)
{
    const int*   batch = (const int*)  d_in[0];
    const float* emb   = (const float*)d_in[1];
    const float* W_ih  = (const float*)d_in[2];
    const float* b_ih  = (const float*)d_in[3];
    const float* W_hh  = (const float*)d_in[4];
    const float* b_hh  = (const float*)d_in[5];
    const float* W_c   = (const float*)d_in[6];
    const float* b_c   = (const float*)d_in[7];
    const float* W_d   = (const float*)d_in[8];
    const float* b_d   = (const float*)d_in[9];
    float* out = (float*)d_out;

    float *embproj, *zbuf, *Pbuf, *avbuf, *decbuf;
    __nv_bfloat16 *phi, *plo, *zthi, *ztlo;
    __nv_bfloat16 *dhi, *dlo, *wdhi, *wdlo, *zhi, *zlo, *avhi, *avlo;
    __nv_bfloat16 *ehi, *elo, *wihhi, *wihlo, *wchi, *wclo;
    cudaGetSymbolAddress((void**)&embproj, g_embproj);
    cudaGetSymbolAddress((void**)&zbuf,    g_z);
    cudaGetSymbolAddress((void**)&Pbuf,    g_P);
    cudaGetSymbolAddress((void**)&avbuf,   g_av);
    cudaGetSymbolAddress((void**)&decbuf,  g_dec);
    cudaGetSymbolAddress((void**)&phi,     g_P_hi);
    cudaGetSymbolAddress((void**)&plo,     g_P_lo);
    cudaGetSymbolAddress((void**)&zthi,    g_zT_hi);
    cudaGetSymbolAddress((void**)&ztlo,    g_zT_lo);
    cudaGetSymbolAddress((void**)&dhi,     g_dec_hi);
    cudaGetSymbolAddress((void**)&dlo,     g_dec_lo);
    cudaGetSymbolAddress((void**)&wdhi,    g_wd_hi);
    cudaGetSymbolAddress((void**)&wdlo,    g_wd_lo);
    cudaGetSymbolAddress((void**)&zhi,     g_z_hi);
    cudaGetSymbolAddress((void**)&zlo,     g_z_lo);
    cudaGetSymbolAddress((void**)&avhi,    g_av_hi);
    cudaGetSymbolAddress((void**)&avlo,    g_av_lo);
    cudaGetSymbolAddress((void**)&ehi,     g_emb_hi);
    cudaGetSymbolAddress((void**)&elo,     g_emb_lo);
    cudaGetSymbolAddress((void**)&wihhi,   g_wih_hi);
    cudaGetSymbolAddress((void**)&wihlo,   g_wih_lo);
    cudaGetSymbolAddress((void**)&wchi,    g_wc_hi);
    cudaGetSymbolAddress((void**)&wclo,    g_wc_lo);

    cudaFuncSetAttribute(hgemm_nt, cudaFuncAttributeMaxDynamicSharedMemorySize, HG_SMEM);

    const int ML = B_ * L_;   // 16384

    // 0. splits of inputs
    split_bf16<<<(V_ * H_ + 1023) / 1024, 1024>>>(emb, ehi, elo, V_ * H_);
    split_bf16<<<(H_ * H_ + 1023) / 1024, 1024>>>(W_ih, wihhi, wihlo, H_ * H_);
    split_bf16<<<(H_ * 2 * H_ + 1023) / 1024, 1024>>>(W_c, wchi, wclo, H_ * 2 * H_);
    split_bf16<<<(V_ * H_ + 1023) / 1024, 1024>>>(W_d, wdhi, wdlo, V_ * H_);

    // 1. embproj[V,H] = emb @ W_ih^T + b_ih  (HMMA split)
    hgemm_nt<<<dim3(4, 79, 1), 256, HG_SMEM>>>(
        ehi, elo, H_, 0, wihhi, wihlo, H_, 0,
        embproj, H_, 0, V_, H_, H_, b_ih, 0);

    // 2. RNN scan -> z fp32 + z bf16 hi/lo (fused split)
    rnn_kernel<<<64, 512>>>(batch, embproj, W_hh, b_hh, zbuf, zhi, zlo);

    // 3. z^T bf16 hi/lo for the P@z NT GEMM
    transpose_split<<<dim3(L_ / 32, H_ / 32, B_), 256>>>(zbuf, zthi, ztlo);

    // 4. scores S = z @ z^T (causal tiles only, HMMA split)
    hgemm_nt<<<dim3(16, 16, B_), 256, HG_SMEM>>>(
        zhi, zlo, H_, LH, zhi, zlo, H_, LH,
        Pbuf, L_, LL, L_, L_, H_, nullptr, 2);

    // 5. row softmax: scores fp32 -> probs bf16 hi/lo
    softmax_rows<<<dim3(L_, B_), 256>>>(Pbuf, phi, plo);

    // 6. av = P @ z  (HMMA split, causal K-limit)
    hgemm_nt<<<dim3(4, 16, B_), 256, HG_SMEM>>>(
        phi, plo, L_, LL, zthi, ztlo, L_, (long long)H_ * L_,
        avbuf, H_, LH, L_, H_, L_, nullptr, 4);

    // 7. fix row 0: uniform attention over all positions
    av0_mean<<<B_, 512>>>(zbuf, avbuf);

    // 8. split av
    split_bf16<<<(ML * H_ + 1023) / 1024, 1024>>>(avbuf, avhi, avlo, ML * H_);

    // 9. dec = av @ W_c[:, :H]^T + b_c ; dec += z @ W_c[:, H:]^T  (HMMA split)
    hgemm_nt<<<dim3(4, 128, 1), 256, HG_SMEM>>>(
        avhi, avlo, H_, 0, wchi, wclo, 2 * H_, 0,
        decbuf, H_, 0, ML, H_, H_, b_c, 0);
    hgemm_nt<<<dim3(4, 128, 1), 256, HG_SMEM>>>(
        zhi, zlo, H_, 0, wchi + H_, wclo + H_, 2 * H_, 0,
        decbuf, H_, 0, ML, H_, H_, nullptr, 1);

    // 10. split dec
    split_bf16<<<(ML * H_ + 1023) / 1024, 1024>>>(decbuf, dhi, dlo, ML * H_);

    // 11. logits = dec @ W_d^T + b_d  (HMMA split)
    hgemm_nt<<<dim3(79, 128, 1), 256, HG_SMEM>>>(
        dhi, dlo, H_, 0, wdhi, wdlo, H_, 0,
        out, V_, 0, ML, V_, H_, b_d, 0);
}

// round 10
// speedup vs baseline: 1.8844x; 1.1046x over previous
#include <cuda_runtime.h>
#include <cuda_bf16.h>
#include <cstdint>

#define B_ 8
#define L_ 2048
#define V_ 10000
#define H_ 512

static const long long LH = (long long)L_ * H_;       // 1048576
static const long long LL = (long long)L_ * L_;       // 4194304

// ---------------- static device scratch (no allocations) ----------------
__device__ float g_embproj[V_ * H_];                   // 20.5 MB
__device__ float g_z[B_ * L_ * H_];                    // 33.5 MB
__device__ float g_P[(size_t)B_ * L_ * L_];            // 134 MB (raw scores)
__device__ float g_av[B_ * L_ * H_];                   // 33.5 MB
__device__ float g_dec[B_ * L_ * H_];                  // 33.5 MB

__device__ __nv_bfloat16 g_P_hi[(size_t)B_ * L_ * L_]; // 67 MB (probs hi)
__device__ __nv_bfloat16 g_P_lo[(size_t)B_ * L_ * L_]; // 67 MB (probs lo)
__device__ __nv_bfloat16 g_zT_hi[B_ * H_ * L_];        // 16.8 MB (z^T)
__device__ __nv_bfloat16 g_zT_lo[B_ * H_ * L_];
__device__ __nv_bfloat16 g_dec_hi[B_ * L_ * H_];
__device__ __nv_bfloat16 g_dec_lo[B_ * L_ * H_];
__device__ __nv_bfloat16 g_wd_hi[V_ * H_];
__device__ __nv_bfloat16 g_wd_lo[V_ * H_];
__device__ __nv_bfloat16 g_z_hi[B_ * L_ * H_];
__device__ __nv_bfloat16 g_z_lo[B_ * L_ * H_];
__device__ __nv_bfloat16 g_av_hi[B_ * L_ * H_];
__device__ __nv_bfloat16 g_av_lo[B_ * L_ * H_];
__device__ __nv_bfloat16 g_emb_hi[V_ * H_];
__device__ __nv_bfloat16 g_emb_lo[V_ * H_];
__device__ __nv_bfloat16 g_wih_hi[H_ * H_];
__device__ __nv_bfloat16 g_wih_lo[H_ * H_];
__device__ __nv_bfloat16 g_wc_hi[H_ * 2 * H_];
__device__ __nv_bfloat16 g_wc_lo[H_ * 2 * H_];

__device__ __forceinline__ uint32_t smem_u32(const void* p) {
    uint32_t a;
    asm("{ .reg .u64 t; cvta.to.shared.u64 t, %1; cvt.u32.u64 %0, t; }"
        : "=r"(a) : "l"(p));
    return a;
}

#define LDSM_X4(r0, r1, r2, r3, addr)                                         \
    asm volatile("ldmatrix.sync.aligned.m8n8.x4.shared.b16 {%0,%1,%2,%3}, [%4];" \
                 : "=r"(r0), "=r"(r1), "=r"(r2), "=r"(r3) : "r"(addr))
#define LDSM_X2(r0, r1, addr)                                                 \
    asm volatile("ldmatrix.sync.aligned.m8n8.x2.shared.b16 {%0,%1}, [%2];"    \
                 : "=r"(r0), "=r"(r1) : "r"(addr))
#define MMA_BF16(c, a, b)                                                     \
    asm volatile("mma.sync.aligned.m16n8k16.row.col.f32.bf16.bf16.f32 "       \
                 "{%0,%1,%2,%3}, {%4,%5,%6,%7}, {%8,%9}, {%0,%1,%2,%3};"      \
                 : "+f"((c)[0]), "+f"((c)[1]), "+f"((c)[2]), "+f"((c)[3])     \
                 : "r"((a)[0]), "r"((a)[1]), "r"((a)[2]), "r"((a)[3]),        \
                   "r"((b)[0]), "r"((b)[1]))

__device__ __forceinline__ void cp16(uint32_t dst, const void* src, bool pred) {
    int sz = pred ? 16 : 0;
    asm volatile("cp.async.cg.shared.global [%0], [%1], 16, %2;"
                 :: "r"(dst), "l"(src), "r"(sz));
}
#define CP_COMMIT() asm volatile("cp.async.commit_group;" ::: "memory")
#define CP_WAIT2()  asm volatile("cp.async.wait_group 2;" ::: "memory")
#define CP_WAIT1()  asm volatile("cp.async.wait_group 1;" ::: "memory")
#define CP_WAIT0()  asm volatile("cp.async.wait_group 0;" ::: "memory")

// ======================================================================
// Generic split-bf16 HMMA NT GEMM (3-stage cp.async pipeline):
//   C[M,N] = (Ahi+Alo)[M,K] @ (Bhi+Blo)[N,K]^T (+bias) (+=C)
// flags: bit0 = accumulate, bit1 = causal tile skip (skip bx > by),
//        bit2 = causal K-limit (K_eff = min(K, (by+1)*128))
// ======================================================================
#define HG_STRIDE 40
#define HG_ARR    (128 * HG_STRIDE)              // 5120 bf16 per array
#define HG_STAGE  (4 * HG_ARR)                   // per stage (Ahi,Alo,Bhi,Blo)
#define HG_NSTG   3
#define HG_SMEM   (HG_NSTG * HG_STAGE * 2)       // 122880 bytes

__global__ __launch_bounds__(256, 1) void hgemm_nt(
    const __nv_bfloat16* __restrict__ Ahi, const __nv_bfloat16* __restrict__ Alo,
    int lda, long long sA,
    const __nv_bfloat16* __restrict__ Bhi, const __nv_bfloat16* __restrict__ Blo,
    int ldb, long long sB,
    float* __restrict__ C, int ldc, long long sC,
    int M, int N, int K,
    const float* __restrict__ bias, int flags)
{
    if ((flags & 2) && blockIdx.x > blockIdx.y) return;
    Ahi += (long long)blockIdx.z * sA;  Alo += (long long)blockIdx.z * sA;
    Bhi += (long long)blockIdx.z * sB;  Blo += (long long)blockIdx.z * sB;
    C   += (long long)blockIdx.z * sC;

    extern __shared__ __nv_bfloat16 sm[];
    const uint32_t smem_base = smem_u32(sm);
    const int tid  = threadIdx.x;
    const int wid  = tid >> 5;
    const int lane = tid & 31;
    const int m0 = blockIdx.y * 128;
    const int n0 = blockIdx.x * 128;
    const int wm = wid >> 2;
    const int wn = wid & 3;
    const int K_eff = (flags & 4) ? min(K, ((int)blockIdx.y + 1) * 128) : K;
    const int nk = K_eff >> 5;

    const int r   = (tid >> 1) & 127;
    const int cc_ = tid & 1;
    const int rowA = m0 + r;
    const int rowB = n0 + r;
    const bool pA = rowA < M;
    const bool pB = rowB < N;
    const long long offA = (long long)(pA ? rowA : M - 1) * lda + cc_ * 16;
    const long long offB = (long long)(pB ? rowB : N - 1) * ldb + cc_ * 16;
    const uint32_t dstoff = (uint32_t)(r * HG_STRIDE + cc_ * 16) * 2;

    auto issue = [&](int kc, int s) {
        const uint32_t db = smem_base + (uint32_t)(s * HG_STAGE) * 2 + dstoff;
        const long long ko = (long long)kc * 32;
        cp16(db + 0 * HG_ARR * 2,      Ahi + offA + ko,     pA);
        cp16(db + 0 * HG_ARR * 2 + 16, Ahi + offA + ko + 8, pA);
        cp16(db + 1 * HG_ARR * 2,      Alo + offA + ko,     pA);
        cp16(db + 1 * HG_ARR * 2 + 16, Alo + offA + ko + 8, pA);
        cp16(db + 2 * HG_ARR * 2,      Bhi + offB + ko,     pB);
        cp16(db + 2 * HG_ARR * 2 + 16, Bhi + offB + ko + 8, pB);
        cp16(db + 3 * HG_ARR * 2,      Blo + offB + ko,     pB);
        cp16(db + 3 * HG_ARR * 2 + 16, Blo + offB + ko + 8, pB);
        CP_COMMIT();
    };

    const int a_row_off = (wm * 64 + (lane & 15)) * HG_STRIDE + (lane >> 4) * 8;
    const int b_row_off = (wn * 32 + (lane & 7)) * HG_STRIDE + ((lane >> 3) & 1) * 8;

    float acc[4][4][4];
#pragma unroll
    for (int i = 0; i < 4; i++)
#pragma unroll
        for (int j = 0; j < 4; j++)
#pragma unroll
            for (int q = 0; q < 4; q++) acc[i][j][q] = 0.f;

    auto compute = [&](int s) {
        const uint32_t base = smem_base + (uint32_t)(s * HG_STAGE) * 2;
#pragma unroll
        for (int kk = 0; kk < 32; kk += 16) {
            uint32_t ah[4][4], al[4][4], bh[4][2], bl[4][2];
#pragma unroll
            for (int mt = 0; mt < 4; mt++) {
                const uint32_t aoff = base + (a_row_off + mt * 16 * HG_STRIDE + kk) * 2;
                LDSM_X4(ah[mt][0], ah[mt][1], ah[mt][2], ah[mt][3], aoff);
                LDSM_X4(al[mt][0], al[mt][1], al[mt][2], al[mt][3], aoff + HG_ARR * 2);
            }
#pragma unroll
            for (int nt = 0; nt < 4; nt++) {
                const uint32_t boff = base + (2 * HG_ARR + b_row_off + nt * 8 * HG_STRIDE + kk) * 2;
                LDSM_X2(bh[nt][0], bh[nt][1], boff);
                LDSM_X2(bl[nt][0], bl[nt][1], boff + HG_ARR * 2);
            }
#pragma unroll
            for (int mt = 0; mt < 4; mt++)
#pragma unroll
                for (int nt = 0; nt < 4; nt++) {
                    MMA_BF16(acc[mt][nt], ah[mt], bh[nt]);
                    MMA_BF16(acc[mt][nt], ah[mt], bl[nt]);
                    MMA_BF16(acc[mt][nt], al[mt], bh[nt]);
                }
        }
    };

    // ---- 3-stage pipeline. Invariant entering compute(kc): group kc done.
    issue(0, 0);
    if (nk > 1) issue(1, 1);
    if (nk > 2) issue(2, 2);
    if (nk > 2)      CP_WAIT2();
    else if (nk > 1) CP_WAIT1();
    else             CP_WAIT0();
    __syncthreads();

    for (int kc = 0; kc < nk; ++kc) {
        compute(kc % 3);
        __syncthreads();
        if (kc + 3 < nk) {
            issue(kc + 3, kc % 3);
            CP_WAIT2();          // outstanding kc+1..kc+3 -> kc+1 done
        } else if (kc + 2 < nk) {
            CP_WAIT1();          // outstanding kc+1,kc+2 -> kc+1 done
        } else {
            CP_WAIT0();          // drain
        }
        __syncthreads();
    }

    // ---- epilogue ----
    const int g  = lane >> 2;
    const int qc = (lane & 3) * 2;
#pragma unroll
    for (int mt = 0; mt < 4; mt++) {
        const int r0 = m0 + wm * 64 + mt * 16 + g;
        if (r0 >= M) continue;
#pragma unroll
        for (int nt = 0; nt < 4; nt++) {
            const int c = n0 + wn * 32 + nt * 8 + qc;
            if (c >= N) continue;
            float bx = 0.f, by = 0.f;
            if (bias) { bx = bias[c]; by = bias[c + 1]; }
            float2 v0 = make_float2(acc[mt][nt][0] + bx, acc[mt][nt][1] + by);
            float2 v1 = make_float2(acc[mt][nt][2] + bx, acc[mt][nt][3] + by);
            float* p0 = C + (long long)r0 * ldc + c;
            float* p1 = C + (long long)(r0 + 8) * ldc + c;
            if (flags & 1) {
                float2 o0 = *(const float2*)p0;
                v0.x += o0.x; v0.y += o0.y;
                if (r0 + 8 < M) {
                    float2 o1 = *(const float2*)p1;
                    v1.x += o1.x; v1.y += o1.y;
                }
            }
            *(float2*)p0 = v0;
            if (r0 + 8 < M) *(float2*)p1 = v1;
        }
    }
}

// ======================================================================
// RNN v2 (column-split): 8-CTA cluster per batch. CTA rank owns the
// k-slice [rank*64, rank*64+64) of h (its OWN outputs from last step —
// no h broadcast needed). Thread t computes the partial for output t
// over that k-slice and pushes ONE remote partial to the owner CTA
// (t>>6) BEFORE the barrier. Owner reduces 8 partials after the barrier.
// Double-buffered partial array; one cluster barrier per step is
// sufficient (fast peers can't re-enter phase p before the owner's
// barrier(s+1) arrival, which follows consumption).
// ======================================================================
__global__ void __cluster_dims__(8, 1, 1) __launch_bounds__(512, 1)
rnn_kernel(const int* __restrict__ batch,
           const float* __restrict__ embproj,
           const float* __restrict__ W_hh,
           const float* __restrict__ b_hh,
           float* __restrict__ z,
           __nv_bfloat16* __restrict__ zhi,
           __nv_bfloat16* __restrict__ zlo)
{
    __shared__ float part[2][8][64];   // [phase][src CTA][slot]
    __shared__ float hloc[64];         // this CTA's own h chunk

    const int t    = threadIdx.x;
    const int rank = blockIdx.x & 7;
    const int b    = blockIdx.x >> 3;
    const int dst  = t >> 6;           // owner CTA of output t
    const int slot = t & 63;

    // W_hh[t][rank*64 + j], j in [0,64)
    float w[64];
    {
        const float* wp = W_hh + (long long)t * H_ + rank * 64;
#pragma unroll
        for (int j = 0; j < 16; j++) {
            float4 v = *(const float4*)(wp + 4 * j);
            w[4*j+0] = v.x; w[4*j+1] = v.y; w[4*j+2] = v.z; w[4*j+3] = v.w;
        }
    }

    float bh = 0.f, xt = 0.f;
    if (t < 64) {
        bh = b_hh[rank * 64 + t];
        hloc[t] = 0.f;                 // h0 = 0
        int tok = batch[b * L_ + 0];
        xt = embproj[(long long)tok * H_ + rank * 64 + t];
    }

    // remote address of part[p][rank][slot] inside CTA 'dst'
    uint32_t rpart[2];
#pragma unroll
    for (int p = 0; p < 2; p++) {
        uint32_t la = (uint32_t)__cvta_generic_to_shared(&part[p][rank][slot]);
        asm volatile("mapa.shared::cluster.u32 %0, %1, %2;"
                     : "=r"(rpart[p]) : "r"(la), "r"(dst));
    }
    __syncthreads();
    // peers' hloc init must be visible before they receive partials? Not
    // needed: partials only touch part[][][]; hloc is CTA-local. But all
    // CTAs must have initialized part-independent state before stores
    // arrive — stores only write part[p][rank][slot], never read remote.
    // A cluster barrier here aligns step counting across CTAs.
    asm volatile("barrier.cluster.arrive.aligned;" ::: "memory");
    asm volatile("barrier.cluster.wait.aligned;"   ::: "memory");

    for (int step = 0; step < L_; ++step) {
        const int p = step & 1;
        // partial over local k-slice (warp-uniform broadcast reads)
        const float4* h4 = (const float4*)hloc;
        float s = 0.f;
#pragma unroll
        for (int j = 0; j < 16; j++) {
            float4 hv = h4[j];
            s = fmaf(w[4*j+0], hv.x, s);
            s = fmaf(w[4*j+1], hv.y, s);
            s = fmaf(w[4*j+2], hv.z, s);
            s = fmaf(w[4*j+3], hv.w, s);
        }
        asm volatile("st.shared::cluster.f32 [%0], %1;"
                     :: "r"(rpart[p]), "f"(s) : "memory");

        // prefetch next x_proj while the barrier settles
        float xtn = 0.f;
        if (t < 64 && step + 1 < L_) {
            int tk = batch[b * L_ + step + 1];
            xtn = embproj[(long long)tk * H_ + rank * 64 + t];
        }

        asm volatile("barrier.cluster.arrive.aligned;" ::: "memory");
        asm volatile("barrier.cluster.wait.aligned;"   ::: "memory");

        if (t < 64) {
            float v = part[p][0][t] + part[p][1][t] + part[p][2][t] + part[p][3][t]
                    + part[p][4][t] + part[p][5][t] + part[p][6][t] + part[p][7][t];
            v = tanhf(xt + v + bh);
            const long long zo = ((long long)(b * L_ + step)) * H_ + rank * 64 + t;
            z[zo] = v;
            __nv_bfloat16 vh = __float2bfloat16(v);
            zhi[zo] = vh;
            zlo[zo] = __float2bfloat16(v - __bfloat162float(vh));
            hloc[t] = v;
        }
        __syncthreads();               // hloc update visible to all warps
        xt = xtn;
    }
}

// ======================================================================
// Row softmax: fp32 scores -> probs bf16 hi/lo (+zero pad to diag tile)
// ======================================================================
__global__ __launch_bounds__(256) void softmax_rows(
    const float* __restrict__ S,
    __nv_bfloat16* __restrict__ Phi, __nv_bfloat16* __restrict__ Plo)
{
    const int i = blockIdx.x;
    const int b = blockIdx.y;
    const float* row = S + (size_t)b * LL + (size_t)i * L_;
    __nv_bfloat16* rh = Phi + (size_t)b * LL + (size_t)i * L_;
    __nv_bfloat16* rl = Plo + (size_t)b * LL + (size_t)i * L_;
    const int len = i;
    const int tileEnd = ((i >> 7) + 1) << 7;
    const int tid = threadIdx.x;

    __shared__ float sm_[8];
    __shared__ float bc[2];

    if (len > 0) {
        float m = -1e30f;
        for (int j = tid; j < len; j += 256) m = fmaxf(m, row[j]);
#pragma unroll
        for (int o = 16; o; o >>= 1) m = fmaxf(m, __shfl_xor_sync(~0u, m, o));
        if ((tid & 31) == 0) sm_[tid >> 5] = m;
        __syncthreads();
        if (tid == 0) {
            float v = sm_[0];
            for (int wgt = 1; wgt < 8; wgt++) v = fmaxf(v, sm_[wgt]);
            bc[0] = v;
        }
        __syncthreads();
        m = bc[0];

        float s = 0.f;
        for (int j = tid; j < len; j += 256) s += expf(row[j] - m);
#pragma unroll
        for (int o = 16; o; o >>= 1) s += __shfl_xor_sync(~0u, s, o);
        if ((tid & 31) == 0) sm_[tid >> 5] = s;
        __syncthreads();
        if (tid == 0) {
            float v = sm_[0];
            for (int wgt = 1; wgt < 8; wgt++) v += sm_[wgt];
            bc[1] = 1.f / v;
        }
        __syncthreads();
        const float inv = bc[1];

        for (int j = tid; j < len; j += 256) {
            float pv = expf(row[j] - m) * inv;
            __nv_bfloat16 h = __float2bfloat16(pv);
            rh[j] = h;
            rl[j] = __float2bfloat16(pv - __bfloat162float(h));
        }
    }
    const __nv_bfloat16 zz = __float2bfloat16(0.f);
    for (int j = len + tid; j < tileEnd; j += 256) { rh[j] = zz; rl[j] = zz; }
}

// ======================================================================
// z [B,L,H] fp32 -> z^T [B,H,L] bf16 hi/lo
// ======================================================================
__global__ __launch_bounds__(256) void transpose_split(
    const float* __restrict__ z,
    __nv_bfloat16* __restrict__ Thi, __nv_bfloat16* __restrict__ Tlo)
{
    __shared__ float tile[32][33];
    const int b  = blockIdx.z;
    const int l0 = blockIdx.x * 32;
    const int h0 = blockIdx.y * 32;
    const int tx = threadIdx.x & 31;
    const int ty = threadIdx.x >> 5;

    const float* zb = z + (size_t)b * LH;
#pragma unroll
    for (int i = ty; i < 32; i += 8)
        tile[i][tx] = zb[(long long)(l0 + i) * H_ + h0 + tx];
    __syncthreads();

    __nv_bfloat16* th = Thi + (size_t)b * H_ * L_;
    __nv_bfloat16* tl = Tlo + (size_t)b * H_ * L_;
#pragma unroll
    for (int i = ty; i < 32; i += 8) {
        float v = tile[tx][i];
        __nv_bfloat16 h = __float2bfloat16(v);
        const long long o = (long long)(h0 + i) * L_ + l0 + tx;
        th[o] = h;
        tl[o] = __float2bfloat16(v - __bfloat162float(h));
    }
}

// ======================================================================
// av row 0 = mean of z
// ======================================================================
__global__ __launch_bounds__(512) void av0_mean(const float* __restrict__ z,
                                                float* __restrict__ av)
{
    const int b = blockIdx.x;
    const float4* zb = (const float4*)(z + (size_t)b * LH);
    const int tid = threadIdx.x;
    const int hc = tid & 127;
    const int jg = tid >> 7;

    float4 acc = make_float4(0.f, 0.f, 0.f, 0.f);
#pragma unroll 8
    for (int j = jg * 512; j < (jg + 1) * 512; j++) {
        float4 v = zb[(long long)j * 128 + hc];
        acc.x += v.x; acc.y += v.y; acc.z += v.z; acc.w += v.w;
    }
    __shared__ float4 part[4][128];
    part[jg][hc] = acc;
    __syncthreads();
    if (tid < 128) {
        float4 s = part[0][tid];
        float4 p1 = part[1][tid], p2 = part[2][tid], p3 = part[3][tid];
        s.x = (s.x + p1.x + p2.x + p3.x) * (1.f / L_);
        s.y = (s.y + p1.y + p2.y + p3.y) * (1.f / L_);
        s.z = (s.z + p1.z + p2.z + p3.z) * (1.f / L_);
        s.w = (s.w + p1.w + p2.w + p3.w) * (1.f / L_);
        ((float4*)(av + (size_t)b * LH))[tid] = s;
    }
}

// ======================================================================
// split fp32 -> (bf16 hi, bf16 lo)
// ======================================================================
__global__ __launch_bounds__(1024) void split_bf16(
    const float* __restrict__ x, __nv_bfloat16* __restrict__ hi,
    __nv_bfloat16* __restrict__ lo, int n)
{
    int i = blockIdx.x * 1024 + threadIdx.x;
    if (i < n) {
        float v = x[i];
        __nv_bfloat16 h = __float2bfloat16(v);
        hi[i] = h;
        lo[i] = __float2bfloat16(v - __bfloat162float(h));
    }
}

// ======================================================================
extern "C" void kernel_launch(void* const* d_in, const int* in_sizes, int n_in,
                              void* d_out, int out_size)
{
    const int*   batch = (const int*)  d_in[0];
    const float* emb   = (const float*)d_in[1];
    const float* W_ih  = (const float*)d_in[2];
    const float* b_ih  = (const float*)d_in[3];
    const float* W_hh  = (const float*)d_in[4];
    const float* b_hh  = (const float*)d_in[5];
    const float* W_c   = (const float*)d_in[6];
    const float* b_c   = (const float*)d_in[7];
    const float* W_d   = (const float*)d_in[8];
    const float* b_d   = (const float*)d_in[9];
    float* out = (float*)d_out;

    float *embproj, *zbuf, *Pbuf, *avbuf, *decbuf;
    __nv_bfloat16 *phi, *plo, *zthi, *ztlo;
    __nv_bfloat16 *dhi, *dlo, *wdhi, *wdlo, *zhi, *zlo, *avhi, *avlo;
    __nv_bfloat16 *ehi, *elo, *wihhi, *wihlo, *wchi, *wclo;
    cudaGetSymbolAddress((void**)&embproj, g_embproj);
    cudaGetSymbolAddress((void**)&zbuf,    g_z);
    cudaGetSymbolAddress((void**)&Pbuf,    g_P);
    cudaGetSymbolAddress((void**)&avbuf,   g_av);
    cudaGetSymbolAddress((void**)&decbuf,  g_dec);
    cudaGetSymbolAddress((void**)&phi,     g_P_hi);
    cudaGetSymbolAddress((void**)&plo,     g_P_lo);
    cudaGetSymbolAddress((void**)&zthi,    g_zT_hi);
    cudaGetSymbolAddress((void**)&ztlo,    g_zT_lo);
    cudaGetSymbolAddress((void**)&dhi,     g_dec_hi);
    cudaGetSymbolAddress((void**)&dlo,     g_dec_lo);
    cudaGetSymbolAddress((void**)&wdhi,    g_wd_hi);
    cudaGetSymbolAddress((void**)&wdlo,    g_wd_lo);
    cudaGetSymbolAddress((void**)&zhi,     g_z_hi);
    cudaGetSymbolAddress((void**)&zlo,     g_z_lo);
    cudaGetSymbolAddress((void**)&avhi,    g_av_hi);
    cudaGetSymbolAddress((void**)&avlo,    g_av_lo);
    cudaGetSymbolAddress((void**)&ehi,     g_emb_hi);
    cudaGetSymbolAddress((void**)&elo,     g_emb_lo);
    cudaGetSymbolAddress((void**)&wihhi,   g_wih_hi);
    cudaGetSymbolAddress((void**)&wihlo,   g_wih_lo);
    cudaGetSymbolAddress((void**)&wchi,    g_wc_hi);
    cudaGetSymbolAddress((void**)&wclo,    g_wc_lo);

    cudaFuncSetAttribute(hgemm_nt, cudaFuncAttributeMaxDynamicSharedMemorySize, HG_SMEM);

    // side stream + events for graph-branch overlap (created once,
    // outside capture — first call is the correctness run)
    static cudaStream_t s2 = nullptr;
    static cudaEvent_t evZ = nullptr, evT = nullptr, evDecZ = nullptr;
    if (!s2) {
        cudaStreamCreateWithFlags(&s2, cudaStreamNonBlocking);
        cudaEventCreateWithFlags(&evZ,    cudaEventDisableTiming);
        cudaEventCreateWithFlags(&evT,    cudaEventDisableTiming);
        cudaEventCreateWithFlags(&evDecZ, cudaEventDisableTiming);
    }

    const int ML = B_ * L_;   // 16384

    // 0. splits of inputs
    split_bf16<<<(V_ * H_ + 1023) / 1024, 1024>>>(emb, ehi, elo, V_ * H_);
    split_bf16<<<(H_ * H_ + 1023) / 1024, 1024>>>(W_ih, wihhi, wihlo, H_ * H_);
    split_bf16<<<(H_ * 2 * H_ + 1023) / 1024, 1024>>>(W_c, wchi, wclo, H_ * 2 * H_);
    split_bf16<<<(V_ * H_ + 1023) / 1024, 1024>>>(W_d, wdhi, wdlo, V_ * H_);

    // 1. embproj[V,H] = emb @ W_ih^T + b_ih
    hgemm_nt<<<dim3(4, 79, 1), 256, HG_SMEM>>>(
        ehi, elo, H_, 0, wihhi, wihlo, H_, 0,
        embproj, H_, 0, V_, H_, H_, b_ih, 0);

    // 2. RNN scan -> z fp32 + z bf16 hi/lo (fused split)
    rnn_kernel<<<64, 512>>>(batch, embproj, W_hh, b_hh, zbuf, zhi, zlo);
    cudaEventRecord(evZ, 0);

    // ---- side branch: transpose + z-part decoder GEMM (with bias) ----
    cudaStreamWaitEvent(s2, evZ, 0);
    transpose_split<<<dim3(L_ / 32, H_ / 32, B_), 256, 0, s2>>>(zbuf, zthi, ztlo);
    cudaEventRecord(evT, s2);
    hgemm_nt<<<dim3(4, 128, 1), 256, HG_SMEM, s2>>>(
        zhi, zlo, H_, 0, wchi + H_, wclo + H_, 2 * H_, 0,
        decbuf, H_, 0, ML, H_, H_, b_c, 0);
    cudaEventRecord(evDecZ, s2);

    // ---- main branch: attention chain ----
    // 4. scores S = z @ z^T (causal tiles only)
    hgemm_nt<<<dim3(16, 16, B_), 256, HG_SMEM>>>(
        zhi, zlo, H_, LH, zhi, zlo, H_, LH,
        Pbuf, L_, LL, L_, L_, H_, nullptr, 2);

    // 5. row softmax: scores fp32 -> probs bf16 hi/lo
    softmax_rows<<<dim3(L_, B_), 256>>>(Pbuf, phi, plo);

    // 6. av = P @ z^T (HMMA split, causal K-limit); needs transpose done
    cudaStreamWaitEvent(0, evT, 0);
    hgemm_nt<<<dim3(4, 16, B_), 256, HG_SMEM>>>(
        phi, plo, L_, LL, zthi, ztlo, L_, (long long)H_ * L_,
        avbuf, H_, LH, L_, H_, L_, nullptr, 4);

    // 7. fix row 0: uniform attention over all positions
    av0_mean<<<B_, 512>>>(zbuf, avbuf);

    // 8. split av
    split_bf16<<<(ML * H_ + 1023) / 1024, 1024>>>(avbuf, avhi, avlo, ML * H_);

    // 9. dec += av @ W_c[:, :H]^T (accumulate onto z-part; join side branch)
    cudaStreamWaitEvent(0, evDecZ, 0);
    hgemm_nt<<<dim3(4, 128, 1), 256, HG_SMEM>>>(
        avhi, avlo, H_, 0, wchi, wclo, 2 * H_, 0,
        decbuf, H_, 0, ML, H_, H_, nullptr, 1);

    // 10. split dec
    split_bf16<<<(ML * H_ + 1023) / 1024, 1024>>>(decbuf, dhi, dlo, ML * H_);

    // 11. logits = dec @ W_d^T + b_d
    hgemm_nt<<<dim3(79, 128, 1), 256, HG_SMEM>>>(
        dhi, dlo, H_, 0, wdhi, wdlo, H_, 0,
        out, V_, 0, ML, V_, H_, b_d, 0);
}

// round 12
// speedup vs baseline: 1.9030x; 1.0099x over previous
#include <cuda_runtime.h>
#include <cuda_bf16.h>
#include <cstdint>

#define B_ 8
#define L_ 2048
#define V_ 10000
#define H_ 512

static const long long LH = (long long)L_ * H_;       // 1048576
static const long long LL = (long long)L_ * L_;       // 4194304

// ---------------- static device scratch (no allocations) ----------------
__device__ float g_embproj[V_ * H_];                   // 20.5 MB
__device__ float g_z[B_ * L_ * H_];                    // 33.5 MB
__device__ float g_P[(size_t)B_ * L_ * L_];            // 134 MB (raw scores)
__device__ float g_dec[B_ * L_ * H_];                  // 33.5 MB

__device__ __nv_bfloat16 g_P_hi[(size_t)B_ * L_ * L_]; // 67 MB (probs hi)
__device__ __nv_bfloat16 g_P_lo[(size_t)B_ * L_ * L_]; // 67 MB (probs lo)
__device__ __nv_bfloat16 g_zT_hi[B_ * H_ * L_];        // 16.8 MB (z^T)
__device__ __nv_bfloat16 g_zT_lo[B_ * H_ * L_];
__device__ __nv_bfloat16 g_dec_hi[B_ * L_ * H_];
__device__ __nv_bfloat16 g_dec_lo[B_ * L_ * H_];
__device__ __nv_bfloat16 g_wd_hi[V_ * H_];
__device__ __nv_bfloat16 g_wd_lo[V_ * H_];
__device__ __nv_bfloat16 g_z_hi[B_ * L_ * H_];
__device__ __nv_bfloat16 g_z_lo[B_ * L_ * H_];
__device__ __nv_bfloat16 g_av_hi[B_ * L_ * H_];
__device__ __nv_bfloat16 g_av_lo[B_ * L_ * H_];
__device__ __nv_bfloat16 g_emb_hi[V_ * H_];
__device__ __nv_bfloat16 g_emb_lo[V_ * H_];
__device__ __nv_bfloat16 g_wih_hi[H_ * H_];
__device__ __nv_bfloat16 g_wih_lo[H_ * H_];
__device__ __nv_bfloat16 g_wc_hi[H_ * 2 * H_];
__device__ __nv_bfloat16 g_wc_lo[H_ * 2 * H_];

__device__ __forceinline__ uint32_t smem_u32(const void* p) {
    uint32_t a;
    asm("{ .reg .u64 t; cvta.to.shared.u64 t, %1; cvt.u32.u64 %0, t; }"
        : "=r"(a) : "l"(p));
    return a;
}

#define LDSM_X4(r0, r1, r2, r3, addr)                                         \
    asm volatile("ldmatrix.sync.aligned.m8n8.x4.shared.b16 {%0,%1,%2,%3}, [%4];" \
                 : "=r"(r0), "=r"(r1), "=r"(r2), "=r"(r3) : "r"(addr))
#define LDSM_X2(r0, r1, addr)                                                 \
    asm volatile("ldmatrix.sync.aligned.m8n8.x2.shared.b16 {%0,%1}, [%2];"    \
                 : "=r"(r0), "=r"(r1) : "r"(addr))
#define MMA_BF16(c, a, b)                                                     \
    asm volatile("mma.sync.aligned.m16n8k16.row.col.f32.bf16.bf16.f32 "       \
                 "{%0,%1,%2,%3}, {%4,%5,%6,%7}, {%8,%9}, {%0,%1,%2,%3};"      \
                 : "+f"((c)[0]), "+f"((c)[1]), "+f"((c)[2]), "+f"((c)[3])     \
                 : "r"((a)[0]), "r"((a)[1]), "r"((a)[2]), "r"((a)[3]),        \
                   "r"((b)[0]), "r"((b)[1]))

__device__ __forceinline__ void cp16(uint32_t dst, const void* src, bool pred) {
    int sz = pred ? 16 : 0;
    asm volatile("cp.async.cg.shared.global [%0], [%1], 16, %2;"
                 :: "r"(dst), "l"(src), "r"(sz));
}
#define CP_COMMIT() asm volatile("cp.async.commit_group;" ::: "memory")
#define CP_WAIT2()  asm volatile("cp.async.wait_group 2;" ::: "memory")
#define CP_WAIT1()  asm volatile("cp.async.wait_group 1;" ::: "memory")
#define CP_WAIT0()  asm volatile("cp.async.wait_group 0;" ::: "memory")

// ======================================================================
// Generic split-bf16 HMMA NT GEMM (3-stage cp.async pipeline):
//   C[M,N] = (Ahi+Alo)[M,K] @ (Bhi+Blo)[N,K]^T (+bias) (+=C)
// flags: bit0 = accumulate (reads fp32 C), bit1 = causal tile skip,
//        bit2 = causal K-limit, bit3 = write output as bf16 hi/lo to
//               Chi/Clo (instead of fp32 C)
// ======================================================================
#define HG_STRIDE 40
#define HG_ARR    (128 * HG_STRIDE)              // 5120 bf16 per array
#define HG_STAGE  (4 * HG_ARR)                   // per stage (Ahi,Alo,Bhi,Blo)
#define HG_NSTG   3
#define HG_SMEM   (HG_NSTG * HG_STAGE * 2)       // 122880 bytes

__global__ __launch_bounds__(256, 1) void hgemm_nt(
    const __nv_bfloat16* __restrict__ Ahi, const __nv_bfloat16* __restrict__ Alo,
    int lda, long long sA,
    const __nv_bfloat16* __restrict__ Bhi, const __nv_bfloat16* __restrict__ Blo,
    int ldb, long long sB,
    float* __restrict__ C,
    __nv_bfloat16* __restrict__ Chi, __nv_bfloat16* __restrict__ Clo,
    int ldc, long long sC,
    int M, int N, int K,
    const float* __restrict__ bias, int flags)
{
    if ((flags & 2) && blockIdx.x > blockIdx.y) return;
    Ahi += (long long)blockIdx.z * sA;  Alo += (long long)blockIdx.z * sA;
    Bhi += (long long)blockIdx.z * sB;  Blo += (long long)blockIdx.z * sB;
    C   += (long long)blockIdx.z * sC;
    if (Chi) { Chi += (long long)blockIdx.z * sC; Clo += (long long)blockIdx.z * sC; }

    extern __shared__ __nv_bfloat16 sm[];
    const uint32_t smem_base = smem_u32(sm);
    const int tid  = threadIdx.x;
    const int wid  = tid >> 5;
    const int lane = tid & 31;
    const int m0 = blockIdx.y * 128;
    const int n0 = blockIdx.x * 128;
    const int wm = wid >> 2;
    const int wn = wid & 3;
    const int K_eff = (flags & 4) ? min(K, ((int)blockIdx.y + 1) * 128) : K;
    const int nk = K_eff >> 5;

    const int r   = (tid >> 1) & 127;
    const int cc_ = tid & 1;
    const int rowA = m0 + r;
    const int rowB = n0 + r;
    const bool pA = rowA < M;
    const bool pB = rowB < N;
    const long long offA = (long long)(pA ? rowA : M - 1) * lda + cc_ * 16;
    const long long offB = (long long)(pB ? rowB : N - 1) * ldb + cc_ * 16;
    const uint32_t dstoff = (uint32_t)(r * HG_STRIDE + cc_ * 16) * 2;

    auto issue = [&](int kc, int s) {
        const uint32_t db = smem_base + (uint32_t)(s * HG_STAGE) * 2 + dstoff;
        const long long ko = (long long)kc * 32;
        cp16(db + 0 * HG_ARR * 2,      Ahi + offA + ko,     pA);
        cp16(db + 0 * HG_ARR * 2 + 16, Ahi + offA + ko + 8, pA);
        cp16(db + 1 * HG_ARR * 2,      Alo + offA + ko,     pA);
        cp16(db + 1 * HG_ARR * 2 + 16, Alo + offA + ko + 8, pA);
        cp16(db + 2 * HG_ARR * 2,      Bhi + offB + ko,     pB);
        cp16(db + 2 * HG_ARR * 2 + 16, Bhi + offB + ko + 8, pB);
        cp16(db + 3 * HG_ARR * 2,      Blo + offB + ko,     pB);
        cp16(db + 3 * HG_ARR * 2 + 16, Blo + offB + ko + 8, pB);
        CP_COMMIT();
    };

    const int a_row_off = (wm * 64 + (lane & 15)) * HG_STRIDE + (lane >> 4) * 8;
    const int b_row_off = (wn * 32 + (lane & 7)) * HG_STRIDE + ((lane >> 3) & 1) * 8;

    float acc[4][4][4];
#pragma unroll
    for (int i = 0; i < 4; i++)
#pragma unroll
        for (int j = 0; j < 4; j++)
#pragma unroll
            for (int q = 0; q < 4; q++) acc[i][j][q] = 0.f;

    auto compute = [&](int s) {
        const uint32_t base = smem_base + (uint32_t)(s * HG_STAGE) * 2;
#pragma unroll
        for (int kk = 0; kk < 32; kk += 16) {
            uint32_t ah[4][4], al[4][4], bh[4][2], bl[4][2];
#pragma unroll
            for (int mt = 0; mt < 4; mt++) {
                const uint32_t aoff = base + (a_row_off + mt * 16 * HG_STRIDE + kk) * 2;
                LDSM_X4(ah[mt][0], ah[mt][1], ah[mt][2], ah[mt][3], aoff);
                LDSM_X4(al[mt][0], al[mt][1], al[mt][2], al[mt][3], aoff + HG_ARR * 2);
            }
#pragma unroll
            for (int nt = 0; nt < 4; nt++) {
                const uint32_t boff = base + (2 * HG_ARR + b_row_off + nt * 8 * HG_STRIDE + kk) * 2;
                LDSM_X2(bh[nt][0], bh[nt][1], boff);
                LDSM_X2(bl[nt][0], bl[nt][1], boff + HG_ARR * 2);
            }
#pragma unroll
            for (int mt = 0; mt < 4; mt++)
#pragma unroll
                for (int nt = 0; nt < 4; nt++) {
                    MMA_BF16(acc[mt][nt], ah[mt], bh[nt]);
                    MMA_BF16(acc[mt][nt], ah[mt], bl[nt]);
                    MMA_BF16(acc[mt][nt], al[mt], bh[nt]);
                }
        }
    };

    // ---- 3-stage pipeline. Invariant entering compute(kc): group kc done.
    issue(0, 0);
    if (nk > 1) issue(1, 1);
    if (nk > 2) issue(2, 2);
    if (nk > 2)      CP_WAIT2();
    else if (nk > 1) CP_WAIT1();
    else             CP_WAIT0();
    __syncthreads();

    for (int kc = 0; kc < nk; ++kc) {
        compute(kc % 3);
        __syncthreads();
        if (kc + 3 < nk) {
            issue(kc + 3, kc % 3);
            CP_WAIT2();
        } else if (kc + 2 < nk) {
            CP_WAIT1();
        } else {
            CP_WAIT0();
        }
        __syncthreads();
    }

    // ---- epilogue ----
    const int g  = lane >> 2;
    const int qc = (lane & 3) * 2;
#pragma unroll
    for (int mt = 0; mt < 4; mt++) {
        const int r0 = m0 + wm * 64 + mt * 16 + g;
        if (r0 >= M) continue;
#pragma unroll
        for (int nt = 0; nt < 4; nt++) {
            const int c = n0 + wn * 32 + nt * 8 + qc;
            if (c >= N) continue;
            float bx = 0.f, by = 0.f;
            if (bias) { bx = bias[c]; by = bias[c + 1]; }
            float2 v0 = make_float2(acc[mt][nt][0] + bx, acc[mt][nt][1] + by);
            float2 v1 = make_float2(acc[mt][nt][2] + bx, acc[mt][nt][3] + by);
            float* p0 = C + (long long)r0 * ldc + c;
            float* p1 = C + (long long)(r0 + 8) * ldc + c;
            if (flags & 1) {
                float2 o0 = *(const float2*)p0;
                v0.x += o0.x; v0.y += o0.y;
                if (r0 + 8 < M) {
                    float2 o1 = *(const float2*)p1;
                    v1.x += o1.x; v1.y += o1.y;
                }
            }
            if (flags & 8) {
                __nv_bfloat162 h2, l2;
                h2.x = __float2bfloat16(v0.x); h2.y = __float2bfloat16(v0.y);
                l2.x = __float2bfloat16(v0.x - __bfloat162float(h2.x));
                l2.y = __float2bfloat16(v0.y - __bfloat162float(h2.y));
                *(__nv_bfloat162*)(Chi + (long long)r0 * ldc + c) = h2;
                *(__nv_bfloat162*)(Clo + (long long)r0 * ldc + c) = l2;
                if (r0 + 8 < M) {
                    h2.x = __float2bfloat16(v1.x); h2.y = __float2bfloat16(v1.y);
                    l2.x = __float2bfloat16(v1.x - __bfloat162float(h2.x));
                    l2.y = __float2bfloat16(v1.y - __bfloat162float(h2.y));
                    *(__nv_bfloat162*)(Chi + (long long)(r0 + 8) * ldc + c) = h2;
                    *(__nv_bfloat162*)(Clo + (long long)(r0 + 8) * ldc + c) = l2;
                }
            } else {
                *(float2*)p0 = v0;
                if (r0 + 8 < M) *(float2*)p1 = v1;
            }
        }
    }
}

// ======================================================================
// RNN (column-split, f32x2 FMA): 8-CTA cluster per batch element.
// ======================================================================
__global__ void __cluster_dims__(8, 1, 1) __launch_bounds__(512, 1)
rnn_kernel(const int* __restrict__ batch,
           const float* __restrict__ embproj,
           const float* __restrict__ W_hh,
           const float* __restrict__ b_hh,
           float* __restrict__ z,
           __nv_bfloat16* __restrict__ zhi,
           __nv_bfloat16* __restrict__ zlo)
{
    __shared__ float part[2][8][64];   // [phase][src CTA][slot]
    __shared__ float hloc[64];         // this CTA's own h chunk

    const int t    = threadIdx.x;
    const int rank = blockIdx.x & 7;
    const int b    = blockIdx.x >> 3;
    const int dst  = t >> 6;           // owner CTA of output t
    const int slot = t & 63;

    // W_hh[t][rank*64 + j] as 32 packed f32x2 pairs
    unsigned long long w2[32];
    {
        const ulonglong2* wp = (const ulonglong2*)(W_hh + (long long)t * H_ + rank * 64);
#pragma unroll
        for (int j = 0; j < 16; j++) {
            ulonglong2 v = wp[j];
            w2[2 * j]     = v.x;
            w2[2 * j + 1] = v.y;
        }
    }

    float bh = 0.f, xt = 0.f;
    if (t < 64) {
        bh = b_hh[rank * 64 + t];
        hloc[t] = 0.f;
        int tok = batch[b * L_ + 0];
        xt = embproj[(long long)tok * H_ + rank * 64 + t];
    }

    uint32_t rpart[2];
#pragma unroll
    for (int p = 0; p < 2; p++) {
        uint32_t la = (uint32_t)__cvta_generic_to_shared(&part[p][rank][slot]);
        asm volatile("mapa.shared::cluster.u32 %0, %1, %2;"
                     : "=r"(rpart[p]) : "r"(la), "r"(dst));
    }
    __syncthreads();
    asm volatile("barrier.cluster.arrive.aligned;" ::: "memory");
    asm volatile("barrier.cluster.wait.aligned;"   ::: "memory");

    for (int step = 0; step < L_; ++step) {
        const int p = step & 1;
        // partial over local k-slice: 32 packed f32x2 FMAs
        const ulonglong2* h2 = (const ulonglong2*)hloc;
        unsigned long long acc = 0ULL;   // (0.f, 0.f)
#pragma unroll
        for (int j = 0; j < 16; j++) {
            ulonglong2 hv = h2[j];
            asm("fma.rn.f32x2 %0, %1, %2, %0;" : "+l"(acc) : "l"(w2[2*j]),   "l"(hv.x));
            asm("fma.rn.f32x2 %0, %1, %2, %0;" : "+l"(acc) : "l"(w2[2*j+1]), "l"(hv.y));
        }
        float sx, sy;
        asm("mov.b64 {%0, %1}, %2;" : "=f"(sx), "=f"(sy) : "l"(acc));
        const float s = sx + sy;
        asm volatile("st.shared::cluster.f32 [%0], %1;"
                     :: "r"(rpart[p]), "f"(s) : "memory");

        float xtn = 0.f;
        if (t < 64 && step + 1 < L_) {
            int tk = batch[b * L_ + step + 1];
            xtn = embproj[(long long)tk * H_ + rank * 64 + t];
        }

        asm volatile("barrier.cluster.arrive.aligned;" ::: "memory");
        asm volatile("barrier.cluster.wait.aligned;"   ::: "memory");

        if (t < 64) {
            float v = part[p][0][t] + part[p][1][t] + part[p][2][t] + part[p][3][t]
                    + part[p][4][t] + part[p][5][t] + part[p][6][t] + part[p][7][t];
            v = tanhf(xt + v + bh);
            const long long zo = ((long long)(b * L_ + step)) * H_ + rank * 64 + t;
            z[zo] = v;
            __nv_bfloat16 vh = __float2bfloat16(v);
            zhi[zo] = vh;
            zlo[zo] = __float2bfloat16(v - __bfloat162float(vh));
            hloc[t] = v;
        }
        __syncthreads();
        xt = xtn;
    }
}

// ======================================================================
// Row softmax: fp32 scores -> probs bf16 hi/lo (+zero pad to diag tile)
// ======================================================================
__global__ __launch_bounds__(256) void softmax_rows(
    const float* __restrict__ S,
    __nv_bfloat16* __restrict__ Phi, __nv_bfloat16* __restrict__ Plo)
{
    const int i = blockIdx.x;
    const int b = blockIdx.y;
    const float* row = S + (size_t)b * LL + (size_t)i * L_;
    __nv_bfloat16* rh = Phi + (size_t)b * LL + (size_t)i * L_;
    __nv_bfloat16* rl = Plo + (size_t)b * LL + (size_t)i * L_;
    const int len = i;
    const int tileEnd = ((i >> 7) + 1) << 7;
    const int tid = threadIdx.x;

    __shared__ float sm_[8];
    __shared__ float bc[2];

    if (len > 0) {
        float m = -1e30f;
        for (int j = tid; j < len; j += 256) m = fmaxf(m, row[j]);
#pragma unroll
        for (int o = 16; o; o >>= 1) m = fmaxf(m, __shfl_xor_sync(~0u, m, o));
        if ((tid & 31) == 0) sm_[tid >> 5] = m;
        __syncthreads();
        if (tid == 0) {
            float v = sm_[0];
            for (int wgt = 1; wgt < 8; wgt++) v = fmaxf(v, sm_[wgt]);
            bc[0] = v;
        }
        __syncthreads();
        m = bc[0];

        float s = 0.f;
        for (int j = tid; j < len; j += 256) s += expf(row[j] - m);
#pragma unroll
        for (int o = 16; o; o >>= 1) s += __shfl_xor_sync(~0u, s, o);
        if ((tid & 31) == 0) sm_[tid >> 5] = s;
        __syncthreads();
        if (tid == 0) {
            float v = sm_[0];
            for (int wgt = 1; wgt < 8; wgt++) v += sm_[wgt];
            bc[1] = 1.f / v;
        }
        __syncthreads();
        const float inv = bc[1];

        for (int j = tid; j < len; j += 256) {
            float pv = expf(row[j] - m) * inv;
            __nv_bfloat16 h = __float2bfloat16(pv);
            rh[j] = h;
            rl[j] = __float2bfloat16(pv - __bfloat162float(h));
        }
    }
    const __nv_bfloat16 zz = __float2bfloat16(0.f);
    for (int j = len + tid; j < tileEnd; j += 256) { rh[j] = zz; rl[j] = zz; }
}

// ======================================================================
// z [B,L,H] fp32 -> z^T [B,H,L] bf16 hi/lo
// ======================================================================
__global__ __launch_bounds__(256) void transpose_split(
    const float* __restrict__ z,
    __nv_bfloat16* __restrict__ Thi, __nv_bfloat16* __restrict__ Tlo)
{
    __shared__ float tile[32][33];
    const int b  = blockIdx.z;
    const int l0 = blockIdx.x * 32;
    const int h0 = blockIdx.y * 32;
    const int tx = threadIdx.x & 31;
    const int ty = threadIdx.x >> 5;

    const float* zb = z + (size_t)b * LH;
#pragma unroll
    for (int i = ty; i < 32; i += 8)
        tile[i][tx] = zb[(long long)(l0 + i) * H_ + h0 + tx];
    __syncthreads();

    __nv_bfloat16* th = Thi + (size_t)b * H_ * L_;
    __nv_bfloat16* tl = Tlo + (size_t)b * H_ * L_;
#pragma unroll
    for (int i = ty; i < 32; i += 8) {
        float v = tile[tx][i];
        __nv_bfloat16 h = __float2bfloat16(v);
        const long long o = (long long)(h0 + i) * L_ + l0 + tx;
        th[o] = h;
        tl[o] = __float2bfloat16(v - __bfloat162float(h));
    }
}

// ======================================================================
// av row 0 = mean of z -> written directly as bf16 hi/lo
// ======================================================================
__global__ __launch_bounds__(512) void av0_mean(const float* __restrict__ z,
                                                __nv_bfloat16* __restrict__ avhi,
                                                __nv_bfloat16* __restrict__ avlo)
{
    const int b = blockIdx.x;
    const float4* zb = (const float4*)(z + (size_t)b * LH);
    const int tid = threadIdx.x;
    const int hc = tid & 127;
    const int jg = tid >> 7;

    float4 acc = make_float4(0.f, 0.f, 0.f, 0.f);
#pragma unroll 8
    for (int j = jg * 512; j < (jg + 1) * 512; j++) {
        float4 v = zb[(long long)j * 128 + hc];
        acc.x += v.x; acc.y += v.y; acc.z += v.z; acc.w += v.w;
    }
    __shared__ float4 part[4][128];
    part[jg][hc] = acc;
    __syncthreads();
    if (tid < 128) {
        float4 s = part[0][tid];
        float4 p1 = part[1][tid], p2 = part[2][tid], p3 = part[3][tid];
        float vv[4];
        vv[0] = (s.x + p1.x + p2.x + p3.x) * (1.f / L_);
        vv[1] = (s.y + p1.y + p2.y + p3.y) * (1.f / L_);
        vv[2] = (s.z + p1.z + p2.z + p3.z) * (1.f / L_);
        vv[3] = (s.w + p1.w + p2.w + p3.w) * (1.f / L_);
        __nv_bfloat16* ah = avhi + (size_t)b * LH + tid * 4;
        __nv_bfloat16* al = avlo + (size_t)b * LH + tid * 4;
#pragma unroll
        for (int q = 0; q < 4; q++) {
            __nv_bfloat16 h = __float2bfloat16(vv[q]);
            ah[q] = h;
            al[q] = __float2bfloat16(vv[q] - __bfloat162float(h));
        }
    }
}

// ======================================================================
// split fp32 -> (bf16 hi, bf16 lo)
// ======================================================================
__global__ __launch_bounds__(1024) void split_bf16(
    const float* __restrict__ x, __nv_bfloat16* __restrict__ hi,
    __nv_bfloat16* __restrict__ lo, int n)
{
    int i = blockIdx.x * 1024 + threadIdx.x;
    if (i < n) {
        float v = x[i];
        __nv_bfloat16 h = __float2bfloat16(v);
        hi[i] = h;
        lo[i] = __float2bfloat16(v - __bfloat162float(h));
    }
}

// ======================================================================
extern "C" void kernel_launch(void* const* d_in, const int* in_sizes, int n_in,
                              void* d_out, int out_size)
{
    const int*   batch = (const int*)  d_in[0];
    const float* emb   = (const float*)d_in[1];
    const float* W_ih  = (const float*)d_in[2];
    const float* b_ih  = (const float*)d_in[3];
    const float* W_hh  = (const float*)d_in[4];
    const float* b_hh  = (const float*)d_in[5];
    const float* W_c   = (const float*)d_in[6];
    const float* b_c   = (const float*)d_in[7];
    const float* W_d   = (const float*)d_in[8];
    const float* b_d   = (const float*)d_in[9];
    float* out = (float*)d_out;

    float *embproj, *zbuf, *Pbuf, *decbuf;
    __nv_bfloat16 *phi, *plo, *zthi, *ztlo;
    __nv_bfloat16 *dhi, *dlo, *wdhi, *wdlo, *zhi, *zlo, *avhi, *avlo;
    __nv_bfloat16 *ehi, *elo, *wihhi, *wihlo, *wchi, *wclo;
    cudaGetSymbolAddress((void**)&embproj, g_embproj);
    cudaGetSymbolAddress((void**)&zbuf,    g_z);
    cudaGetSymbolAddress((void**)&Pbuf,    g_P);
    cudaGetSymbolAddress((void**)&decbuf,  g_dec);
    cudaGetSymbolAddress((void**)&phi,     g_P_hi);
    cudaGetSymbolAddress((void**)&plo,     g_P_lo);
    cudaGetSymbolAddress((void**)&zthi,    g_zT_hi);
    cudaGetSymbolAddress((void**)&ztlo,    g_zT_lo);
    cudaGetSymbolAddress((void**)&dhi,     g_dec_hi);
    cudaGetSymbolAddress((void**)&dlo,     g_dec_lo);
    cudaGetSymbolAddress((void**)&wdhi,    g_wd_hi);
    cudaGetSymbolAddress((void**)&wdlo,    g_wd_lo);
    cudaGetSymbolAddress((void**)&zhi,     g_z_hi);
    cudaGetSymbolAddress((void**)&zlo,     g_z_lo);
    cudaGetSymbolAddress((void**)&avhi,    g_av_hi);
    cudaGetSymbolAddress((void**)&avlo,    g_av_lo);
    cudaGetSymbolAddress((void**)&ehi,     g_emb_hi);
    cudaGetSymbolAddress((void**)&elo,     g_emb_lo);
    cudaGetSymbolAddress((void**)&wihhi,   g_wih_hi);
    cudaGetSymbolAddress((void**)&wihlo,   g_wih_lo);
    cudaGetSymbolAddress((void**)&wchi,    g_wc_hi);
    cudaGetSymbolAddress((void**)&wclo,    g_wc_lo);

    cudaFuncSetAttribute(hgemm_nt, cudaFuncAttributeMaxDynamicSharedMemorySize, HG_SMEM);

    static cudaStream_t s2 = nullptr;
    static cudaEvent_t evZ = nullptr, evT = nullptr, evDecZ = nullptr;
    if (!s2) {
        cudaStreamCreateWithFlags(&s2, cudaStreamNonBlocking);
        cudaEventCreateWithFlags(&evZ,    cudaEventDisableTiming);
        cudaEventCreateWithFlags(&evT,    cudaEventDisableTiming);
        cudaEventCreateWithFlags(&evDecZ, cudaEventDisableTiming);
    }

    const int ML = B_ * L_;   // 16384

    // ---- side stream: W_c / W_d splits overlap with the main head ----
    split_bf16<<<(H_ * 2 * H_ + 1023) / 1024, 1024, 0, s2>>>(W_c, wchi, wclo, H_ * 2 * H_);
    split_bf16<<<(V_ * H_ + 1023) / 1024, 1024, 0, s2>>>(W_d, wdhi, wdlo, V_ * H_);

    // ---- main: emb/W_ih splits -> embproj -> RNN ----
    split_bf16<<<(V_ * H_ + 1023) / 1024, 1024>>>(emb, ehi, elo, V_ * H_);
    split_bf16<<<(H_ * H_ + 1023) / 1024, 1024>>>(W_ih, wihhi, wihlo, H_ * H_);

    hgemm_nt<<<dim3(4, 79, 1), 256, HG_SMEM>>>(
        ehi, elo, H_, 0, wihhi, wihlo, H_, 0,
        embproj, nullptr, nullptr, H_, 0, V_, H_, H_, b_ih, 0);

    rnn_kernel<<<64, 512>>>(batch, embproj, W_hh, b_hh, zbuf, zhi, zlo);
    cudaEventRecord(evZ, 0);

    // ---- side branch: transpose + z-part decoder GEMM (with bias) ----
    cudaStreamWaitEvent(s2, evZ, 0);
    transpose_split<<<dim3(L_ / 32, H_ / 32, B_), 256, 0, s2>>>(zbuf, zthi, ztlo);
    cudaEventRecord(evT, s2);
    hgemm_nt<<<dim3(4, 128, 1), 256, HG_SMEM, s2>>>(
        zhi, zlo, H_, 0, wchi + H_, wclo + H_, 2 * H_, 0,
        decbuf, nullptr, nullptr, H_, 0, ML, H_, H_, b_c, 0);
    cudaEventRecord(evDecZ, s2);

    // ---- main branch: attention chain ----
    hgemm_nt<<<dim3(16, 16, B_), 256, HG_SMEM>>>(
        zhi, zlo, H_, LH, zhi, zlo, H_, LH,
        Pbuf, nullptr, nullptr, L_, LL, L_, L_, H_, nullptr, 2);

    softmax_rows<<<dim3(L_, B_), 256>>>(Pbuf, phi, plo);

    // av = P @ z^T  (causal K-limit, fused bf16-split output)
    cudaStreamWaitEvent(0, evT, 0);
    hgemm_nt<<<dim3(4, 16, B_), 256, HG_SMEM>>>(
        phi, plo, L_, LL, zthi, ztlo, L_, (long long)H_ * L_,
        nullptr, avhi, avlo, H_, LH, L_, H_, L_, nullptr, 4 | 8);

    // fix row 0: uniform attention -> mean of z, written as hi/lo
    av0_mean<<<B_, 512>>>(zbuf, avhi, avlo);

    // dec += av @ W_c[:, :H]^T  (accumulate fp32 dec, emit bf16 hi/lo)
    cudaStreamWaitEvent(0, evDecZ, 0);
    hgemm_nt<<<dim3(4, 128, 1), 256, HG_SMEM>>>(
        avhi, avlo, H_, 0, wchi, wclo, 2 * H_, 0,
        decbuf, dhi, dlo, H_, 0, ML, H_, H_, nullptr, 1 | 8);

    // logits = dec @ W_d^T + b_d
    hgemm_nt<<<dim3(79, 128, 1), 256, HG_SMEM>>>(
        dhi, dlo, H_, 0, wdhi, wdlo, H_, 0,
        out, nullptr, nullptr, V_, 0, ML, V_, H_, b_d, 0);
}

// round 13
// speedup vs baseline: 2.1153x; 1.1115x over previous
#include <cuda_runtime.h>
#include <cuda_bf16.h>
#include <cstdint>

#define B_ 8
#define L_ 2048
#define V_ 10000
#define H_ 512

static const long long LH = (long long)L_ * H_;       // 1048576
static const long long LL = (long long)L_ * L_;       // 4194304

// ---------------- static device scratch (no allocations) ----------------
__device__ float g_embproj[V_ * H_];                   // 20.5 MB
__device__ float g_z[B_ * L_ * H_];                    // 33.5 MB
__device__ float g_P[(size_t)B_ * L_ * L_];            // 134 MB (raw scores)
__device__ float g_dec[B_ * L_ * H_];                  // 33.5 MB

__device__ __nv_bfloat16 g_P_hi[(size_t)B_ * L_ * L_]; // 67 MB (probs hi)
__device__ __nv_bfloat16 g_P_lo[(size_t)B_ * L_ * L_]; // 67 MB (probs lo)
__device__ __nv_bfloat16 g_zT_hi[B_ * H_ * L_];        // 16.8 MB (z^T)
__device__ __nv_bfloat16 g_zT_lo[B_ * H_ * L_];
__device__ __nv_bfloat16 g_dec_hi[B_ * L_ * H_];
__device__ __nv_bfloat16 g_dec_lo[B_ * L_ * H_];
__device__ __nv_bfloat16 g_wd_hi[V_ * H_];
__device__ __nv_bfloat16 g_wd_lo[V_ * H_];
__device__ __nv_bfloat16 g_z_hi[B_ * L_ * H_];
__device__ __nv_bfloat16 g_z_lo[B_ * L_ * H_];
__device__ __nv_bfloat16 g_av_hi[B_ * L_ * H_];
__device__ __nv_bfloat16 g_av_lo[B_ * L_ * H_];
__device__ __nv_bfloat16 g_emb_hi[V_ * H_];
__device__ __nv_bfloat16 g_emb_lo[V_ * H_];
__device__ __nv_bfloat16 g_wih_hi[H_ * H_];
__device__ __nv_bfloat16 g_wih_lo[H_ * H_];
__device__ __nv_bfloat16 g_wc_hi[H_ * 2 * H_];
__device__ __nv_bfloat16 g_wc_lo[H_ * 2 * H_];

__device__ __forceinline__ uint32_t smem_u32(const void* p) {
    uint32_t a;
    asm("{ .reg .u64 t; cvta.to.shared.u64 t, %1; cvt.u32.u64 %0, t; }"
        : "=r"(a) : "l"(p));
    return a;
}

#define LDSM_X4(r0, r1, r2, r3, addr)                                         \
    asm volatile("ldmatrix.sync.aligned.m8n8.x4.shared.b16 {%0,%1,%2,%3}, [%4];" \
                 : "=r"(r0), "=r"(r1), "=r"(r2), "=r"(r3) : "r"(addr))
#define LDSM_X2(r0, r1, addr)                                                 \
    asm volatile("ldmatrix.sync.aligned.m8n8.x2.shared.b16 {%0,%1}, [%2];"    \
                 : "=r"(r0), "=r"(r1) : "r"(addr))
#define MMA_BF16(c, a, b)                                                     \
    asm volatile("mma.sync.aligned.m16n8k16.row.col.f32.bf16.bf16.f32 "       \
                 "{%0,%1,%2,%3}, {%4,%5,%6,%7}, {%8,%9}, {%0,%1,%2,%3};"      \
                 : "+f"((c)[0]), "+f"((c)[1]), "+f"((c)[2]), "+f"((c)[3])     \
                 : "r"((a)[0]), "r"((a)[1]), "r"((a)[2]), "r"((a)[3]),        \
                   "r"((b)[0]), "r"((b)[1]))

__device__ __forceinline__ void cp16(uint32_t dst, const void* src, bool pred) {
    int sz = pred ? 16 : 0;
    asm volatile("cp.async.cg.shared.global [%0], [%1], 16, %2;"
                 :: "r"(dst), "l"(src), "r"(sz));
}
#define CP_COMMIT() asm volatile("cp.async.commit_group;" ::: "memory")
#define CP_WAIT1()  asm volatile("cp.async.wait_group 1;" ::: "memory")
#define CP_WAIT0()  asm volatile("cp.async.wait_group 0;" ::: "memory")

// ======================================================================
// Generic split-bf16 HMMA NT GEMM (2-stage cp.async, 2 CTAs/SM):
//   C[M,N] = (Ahi+Alo)[M,K] @ (Bhi+Blo)[N,K]^T (+bias) (+=C)
// flags: bit0 = accumulate (reads fp32 C), bit1 = causal tile skip,
//        bit2 = causal K-limit, bit3 = write output as bf16 hi/lo
// ======================================================================
#define HG_STRIDE 40
#define HG_ARR    (128 * HG_STRIDE)              // 5120 bf16 per array
#define HG_STAGE  (4 * HG_ARR)                   // per stage (Ahi,Alo,Bhi,Blo)
#define HG_SMEM   (2 * HG_STAGE * 2)             // 81920 bytes (2 stages)

__global__ __launch_bounds__(256, 2) void hgemm_nt(
    const __nv_bfloat16* __restrict__ Ahi, const __nv_bfloat16* __restrict__ Alo,
    int lda, long long sA,
    const __nv_bfloat16* __restrict__ Bhi, const __nv_bfloat16* __restrict__ Blo,
    int ldb, long long sB,
    float* __restrict__ C,
    __nv_bfloat16* __restrict__ Chi, __nv_bfloat16* __restrict__ Clo,
    int ldc, long long sC,
    int M, int N, int K,
    const float* __restrict__ bias, int flags)
{
    if ((flags & 2) && blockIdx.x > blockIdx.y) return;
    Ahi += (long long)blockIdx.z * sA;  Alo += (long long)blockIdx.z * sA;
    Bhi += (long long)blockIdx.z * sB;  Blo += (long long)blockIdx.z * sB;
    C   += (long long)blockIdx.z * sC;
    if (Chi) { Chi += (long long)blockIdx.z * sC; Clo += (long long)blockIdx.z * sC; }

    extern __shared__ __nv_bfloat16 sm[];
    const uint32_t smem_base = smem_u32(sm);
    const int tid  = threadIdx.x;
    const int wid  = tid >> 5;
    const int lane = tid & 31;
    const int m0 = blockIdx.y * 128;
    const int n0 = blockIdx.x * 128;
    const int wm = wid >> 2;
    const int wn = wid & 3;
    const int K_eff = (flags & 4) ? min(K, ((int)blockIdx.y + 1) * 128) : K;
    const int nk = K_eff >> 5;

    const int r   = (tid >> 1) & 127;
    const int cc_ = tid & 1;
    const int rowA = m0 + r;
    const int rowB = n0 + r;
    const bool pA = rowA < M;
    const bool pB = rowB < N;
    const long long offA = (long long)(pA ? rowA : M - 1) * lda + cc_ * 16;
    const long long offB = (long long)(pB ? rowB : N - 1) * ldb + cc_ * 16;
    const uint32_t dstoff = (uint32_t)(r * HG_STRIDE + cc_ * 16) * 2;

    auto issue = [&](int kc, int s) {
        const uint32_t db = smem_base + (uint32_t)(s * HG_STAGE) * 2 + dstoff;
        const long long ko = (long long)kc * 32;
        cp16(db + 0 * HG_ARR * 2,      Ahi + offA + ko,     pA);
        cp16(db + 0 * HG_ARR * 2 + 16, Ahi + offA + ko + 8, pA);
        cp16(db + 1 * HG_ARR * 2,      Alo + offA + ko,     pA);
        cp16(db + 1 * HG_ARR * 2 + 16, Alo + offA + ko + 8, pA);
        cp16(db + 2 * HG_ARR * 2,      Bhi + offB + ko,     pB);
        cp16(db + 2 * HG_ARR * 2 + 16, Bhi + offB + ko + 8, pB);
        cp16(db + 3 * HG_ARR * 2,      Blo + offB + ko,     pB);
        cp16(db + 3 * HG_ARR * 2 + 16, Blo + offB + ko + 8, pB);
        CP_COMMIT();
    };

    const int a_row_off = (wm * 64 + (lane & 15)) * HG_STRIDE + (lane >> 4) * 8;
    const int b_row_off = (wn * 32 + (lane & 7)) * HG_STRIDE + ((lane >> 3) & 1) * 8;

    float acc[4][4][4];
#pragma unroll
    for (int i = 0; i < 4; i++)
#pragma unroll
        for (int j = 0; j < 4; j++)
#pragma unroll
            for (int q = 0; q < 4; q++) acc[i][j][q] = 0.f;

    // Restructured for register economy: B frags resident (16 regs),
    // A frags streamed per mt (8 live) -> fits 128-reg budget @occ 2.
    auto compute = [&](int s) {
        const uint32_t base = smem_base + (uint32_t)(s * HG_STAGE) * 2;
#pragma unroll
        for (int kk = 0; kk < 32; kk += 16) {
            uint32_t bh[4][2], bl[4][2];
#pragma unroll
            for (int nt = 0; nt < 4; nt++) {
                const uint32_t boff = base + (2 * HG_ARR + b_row_off + nt * 8 * HG_STRIDE + kk) * 2;
                LDSM_X2(bh[nt][0], bh[nt][1], boff);
                LDSM_X2(bl[nt][0], bl[nt][1], boff + HG_ARR * 2);
            }
#pragma unroll
            for (int mt = 0; mt < 4; mt++) {
                uint32_t ah[4], al[4];
                const uint32_t aoff = base + (a_row_off + mt * 16 * HG_STRIDE + kk) * 2;
                LDSM_X4(ah[0], ah[1], ah[2], ah[3], aoff);
                LDSM_X4(al[0], al[1], al[2], al[3], aoff + HG_ARR * 2);
#pragma unroll
                for (int nt = 0; nt < 4; nt++) {
                    MMA_BF16(acc[mt][nt], ah, bh[nt]);
                    MMA_BF16(acc[mt][nt], ah, bl[nt]);
                    MMA_BF16(acc[mt][nt], al, bh[nt]);
                }
            }
        }
    };

    // ---- 2-stage pipeline (R8-proven wait logic). ----
    issue(0, 0);
    if (nk > 1) { issue(1, 1); CP_WAIT1(); }
    else        { CP_WAIT0(); }
    __syncthreads();

    for (int kc = 0; kc < nk; ++kc) {
        const int p = kc & 1;
        compute(p);
        __syncthreads();
        if (kc + 2 < nk) {
            issue(kc + 2, p);
            CP_WAIT1();
        } else {
            CP_WAIT0();
        }
        __syncthreads();
    }

    // ---- epilogue ----
    const int g  = lane >> 2;
    const int qc = (lane & 3) * 2;
#pragma unroll
    for (int mt = 0; mt < 4; mt++) {
        const int r0 = m0 + wm * 64 + mt * 16 + g;
        if (r0 >= M) continue;
#pragma unroll
        for (int nt = 0; nt < 4; nt++) {
            const int c = n0 + wn * 32 + nt * 8 + qc;
            if (c >= N) continue;
            float bx = 0.f, by = 0.f;
            if (bias) { bx = bias[c]; by = bias[c + 1]; }
            float2 v0 = make_float2(acc[mt][nt][0] + bx, acc[mt][nt][1] + by);
            float2 v1 = make_float2(acc[mt][nt][2] + bx, acc[mt][nt][3] + by);
            float* p0 = C + (long long)r0 * ldc + c;
            float* p1 = C + (long long)(r0 + 8) * ldc + c;
            if (flags & 1) {
                float2 o0 = *(const float2*)p0;
                v0.x += o0.x; v0.y += o0.y;
                if (r0 + 8 < M) {
                    float2 o1 = *(const float2*)p1;
                    v1.x += o1.x; v1.y += o1.y;
                }
            }
            if (flags & 8) {
                __nv_bfloat162 h2, l2;
                h2.x = __float2bfloat16(v0.x); h2.y = __float2bfloat16(v0.y);
                l2.x = __float2bfloat16(v0.x - __bfloat162float(h2.x));
                l2.y = __float2bfloat16(v0.y - __bfloat162float(h2.y));
                *(__nv_bfloat162*)(Chi + (long long)r0 * ldc + c) = h2;
                *(__nv_bfloat162*)(Clo + (long long)r0 * ldc + c) = l2;
                if (r0 + 8 < M) {
                    h2.x = __float2bfloat16(v1.x); h2.y = __float2bfloat16(v1.y);
                    l2.x = __float2bfloat16(v1.x - __bfloat162float(h2.x));
                    l2.y = __float2bfloat16(v1.y - __bfloat162float(h2.y));
                    *(__nv_bfloat162*)(Chi + (long long)(r0 + 8) * ldc + c) = h2;
                    *(__nv_bfloat162*)(Clo + (long long)(r0 + 8) * ldc + c) = l2;
                }
            } else {
                *(float2*)p0 = v0;
                if (r0 + 8 < M) *(float2*)p1 = v1;
            }
        }
    }
}

// ======================================================================
// RNN (column-split, f32x2 FMA): 8-CTA cluster per batch element.
// ======================================================================
__global__ void __cluster_dims__(8, 1, 1) __launch_bounds__(512, 1)
rnn_kernel(const int* __restrict__ batch,
           const float* __restrict__ embproj,
           const float* __restrict__ W_hh,
           const float* __restrict__ b_hh,
           float* __restrict__ z,
           __nv_bfloat16* __restrict__ zhi,
           __nv_bfloat16* __restrict__ zlo)
{
    __shared__ float part[2][8][64];   // [phase][src CTA][slot]
    __shared__ float hloc[64];         // this CTA's own h chunk

    const int t    = threadIdx.x;
    const int rank = blockIdx.x & 7;
    const int b    = blockIdx.x >> 3;
    const int dst  = t >> 6;           // owner CTA of output t
    const int slot = t & 63;

    unsigned long long w2[32];
    {
        const ulonglong2* wp = (const ulonglong2*)(W_hh + (long long)t * H_ + rank * 64);
#pragma unroll
        for (int j = 0; j < 16; j++) {
            ulonglong2 v = wp[j];
            w2[2 * j]     = v.x;
            w2[2 * j + 1] = v.y;
        }
    }

    float bh = 0.f, xt = 0.f;
    if (t < 64) {
        bh = b_hh[rank * 64 + t];
        hloc[t] = 0.f;
        int tok = batch[b * L_ + 0];
        xt = embproj[(long long)tok * H_ + rank * 64 + t];
    }

    uint32_t rpart[2];
#pragma unroll
    for (int p = 0; p < 2; p++) {
        uint32_t la = (uint32_t)__cvta_generic_to_shared(&part[p][rank][slot]);
        asm volatile("mapa.shared::cluster.u32 %0, %1, %2;"
                     : "=r"(rpart[p]) : "r"(la), "r"(dst));
    }
    __syncthreads();
    asm volatile("barrier.cluster.arrive.aligned;" ::: "memory");
    asm volatile("barrier.cluster.wait.aligned;"   ::: "memory");

    for (int step = 0; step < L_; ++step) {
        const int p = step & 1;
        const ulonglong2* h2 = (const ulonglong2*)hloc;
        unsigned long long acc = 0ULL;
#pragma unroll
        for (int j = 0; j < 16; j++) {
            ulonglong2 hv = h2[j];
            asm("fma.rn.f32x2 %0, %1, %2, %0;" : "+l"(acc) : "l"(w2[2*j]),   "l"(hv.x));
            asm("fma.rn.f32x2 %0, %1, %2, %0;" : "+l"(acc) : "l"(w2[2*j+1]), "l"(hv.y));
        }
        float sx, sy;
        asm("mov.b64 {%0, %1}, %2;" : "=f"(sx), "=f"(sy) : "l"(acc));
        const float s = sx + sy;
        asm volatile("st.shared::cluster.f32 [%0], %1;"
                     :: "r"(rpart[p]), "f"(s) : "memory");

        float xtn = 0.f;
        if (t < 64 && step + 1 < L_) {
            int tk = batch[b * L_ + step + 1];
            xtn = embproj[(long long)tk * H_ + rank * 64 + t];
        }

        asm volatile("barrier.cluster.arrive.aligned;" ::: "memory");
        asm volatile("barrier.cluster.wait.aligned;"   ::: "memory");

        if (t < 64) {
            float v = part[p][0][t] + part[p][1][t] + part[p][2][t] + part[p][3][t]
                    + part[p][4][t] + part[p][5][t] + part[p][6][t] + part[p][7][t];
            v = tanhf(xt + v + bh);
            const long long zo = ((long long)(b * L_ + step)) * H_ + rank * 64 + t;
            z[zo] = v;
            __nv_bfloat16 vh = __float2bfloat16(v);
            zhi[zo] = vh;
            zlo[zo] = __float2bfloat16(v - __bfloat162float(vh));
            hloc[t] = v;
        }
        __syncthreads();
        xt = xtn;
    }
}

// ======================================================================
// Row softmax: fp32 scores -> probs bf16 hi/lo (+zero pad to diag tile)
// ======================================================================
__global__ __launch_bounds__(256) void softmax_rows(
    const float* __restrict__ S,
    __nv_bfloat16* __restrict__ Phi, __nv_bfloat16* __restrict__ Plo)
{
    const int i = blockIdx.x;
    const int b = blockIdx.y;
    const float* row = S + (size_t)b * LL + (size_t)i * L_;
    __nv_bfloat16* rh = Phi + (size_t)b * LL + (size_t)i * L_;
    __nv_bfloat16* rl = Plo + (size_t)b * LL + (size_t)i * L_;
    const int len = i;
    const int tileEnd = ((i >> 7) + 1) << 7;
    const int tid = threadIdx.x;

    __shared__ float sm_[8];
    __shared__ float bc[2];

    if (len > 0) {
        float m = -1e30f;
        for (int j = tid; j < len; j += 256) m = fmaxf(m, row[j]);
#pragma unroll
        for (int o = 16; o; o >>= 1) m = fmaxf(m, __shfl_xor_sync(~0u, m, o));
        if ((tid & 31) == 0) sm_[tid >> 5] = m;
        __syncthreads();
        if (tid == 0) {
            float v = sm_[0];
            for (int wgt = 1; wgt < 8; wgt++) v = fmaxf(v, sm_[wgt]);
            bc[0] = v;
        }
        __syncthreads();
        m = bc[0];

        float s = 0.f;
        for (int j = tid; j < len; j += 256) s += expf(row[j] - m);
#pragma unroll
        for (int o = 16; o; o >>= 1) s += __shfl_xor_sync(~0u, s, o);
        if ((tid & 31) == 0) sm_[tid >> 5] = s;
        __syncthreads();
        if (tid == 0) {
            float v = sm_[0];
            for (int wgt = 1; wgt < 8; wgt++) v += sm_[wgt];
            bc[1] = 1.f / v;
        }
        __syncthreads();
        const float inv = bc[1];

        for (int j = tid; j < len; j += 256) {
            float pv = expf(row[j] - m) * inv;
            __nv_bfloat16 h = __float2bfloat16(pv);
            rh[j] = h;
            rl[j] = __float2bfloat16(pv - __bfloat162float(h));
        }
    }
    const __nv_bfloat16 zz = __float2bfloat16(0.f);
    for (int j = len + tid; j < tileEnd; j += 256) { rh[j] = zz; rl[j] = zz; }
}

// ======================================================================
// z [B,L,H] fp32 -> z^T [B,H,L] bf16 hi/lo
// ======================================================================
__global__ __launch_bounds__(256) void transpose_split(
    const float* __restrict__ z,
    __nv_bfloat16* __restrict__ Thi, __nv_bfloat16* __restrict__ Tlo)
{
    __shared__ float tile[32][33];
    const int b  = blockIdx.z;
    const int l0 = blockIdx.x * 32;
    const int h0 = blockIdx.y * 32;
    const int tx = threadIdx.x & 31;
    const int ty = threadIdx.x >> 5;

    const float* zb = z + (size_t)b * LH;
#pragma unroll
    for (int i = ty; i < 32; i += 8)
        tile[i][tx] = zb[(long long)(l0 + i) * H_ + h0 + tx];
    __syncthreads();

    __nv_bfloat16* th = Thi + (size_t)b * H_ * L_;
    __nv_bfloat16* tl = Tlo + (size_t)b * H_ * L_;
#pragma unroll
    for (int i = ty; i < 32; i += 8) {
        float v = tile[tx][i];
        __nv_bfloat16 h = __float2bfloat16(v);
        const long long o = (long long)(h0 + i) * L_ + l0 + tx;
        th[o] = h;
        tl[o] = __float2bfloat16(v - __bfloat162float(h));
    }
}

// ======================================================================
// av row 0 = mean of z -> written directly as bf16 hi/lo
// ======================================================================
__global__ __launch_bounds__(512) void av0_mean(const float* __restrict__ z,
                                                __nv_bfloat16* __restrict__ avhi,
                                                __nv_bfloat16* __restrict__ avlo)
{
    const int b = blockIdx.x;
    const float4* zb = (const float4*)(z + (size_t)b * LH);
    const int tid = threadIdx.x;
    const int hc = tid & 127;
    const int jg = tid >> 7;

    float4 acc = make_float4(0.f, 0.f, 0.f, 0.f);
#pragma unroll 8
    for (int j = jg * 512; j < (jg + 1) * 512; j++) {
        float4 v = zb[(long long)j * 128 + hc];
        acc.x += v.x; acc.y += v.y; acc.z += v.z; acc.w += v.w;
    }
    __shared__ float4 part[4][128];
    part[jg][hc] = acc;
    __syncthreads();
    if (tid < 128) {
        float4 s = part[0][tid];
        float4 p1 = part[1][tid], p2 = part[2][tid], p3 = part[3][tid];
        float vv[4];
        vv[0] = (s.x + p1.x + p2.x + p3.x) * (1.f / L_);
        vv[1] = (s.y + p1.y + p2.y + p3.y) * (1.f / L_);
        vv[2] = (s.z + p1.z + p2.z + p3.z) * (1.f / L_);
        vv[3] = (s.w + p1.w + p2.w + p3.w) * (1.f / L_);
        __nv_bfloat16* ah = avhi + (size_t)b * LH + tid * 4;
        __nv_bfloat16* al = avlo + (size_t)b * LH + tid * 4;
#pragma unroll
        for (int q = 0; q < 4; q++) {
            __nv_bfloat16 h = __float2bfloat16(vv[q]);
            ah[q] = h;
            al[q] = __float2bfloat16(vv[q] - __bfloat162float(h));
        }
    }
}

// ======================================================================
// split fp32 -> (bf16 hi, bf16 lo)
// ======================================================================
__global__ __launch_bounds__(1024) void split_bf16(
    const float* __restrict__ x, __nv_bfloat16* __restrict__ hi,
    __nv_bfloat16* __restrict__ lo, int n)
{
    int i = blockIdx.x * 1024 + threadIdx.x;
    if (i < n) {
        float v = x[i];
        __nv_bfloat16 h = __float2bfloat16(v);
        hi[i] = h;
        lo[i] = __float2bfloat16(v - __bfloat162float(h));
    }
}

// ======================================================================
extern "C" void kernel_launch(void* const* d_in, const int* in_sizes, int n_in,
                              void* d_out, int out_size)
{
    const int*   batch = (const int*)  d_in[0];
    const float* emb   = (const float*)d_in[1];
    const float* W_ih  = (const float*)d_in[2];
    const float* b_ih  = (const float*)d_in[3];
    const float* W_hh  = (const float*)d_in[4];
    const float* b_hh  = (const float*)d_in[5];
    const float* W_c   = (const float*)d_in[6];
    const float* b_c   = (const float*)d_in[7];
    const float* W_d   = (const float*)d_in[8];
    const float* b_d   = (const float*)d_in[9];
    float* out = (float*)d_out;

    float *embproj, *zbuf, *Pbuf, *decbuf;
    __nv_bfloat16 *phi, *plo, *zthi, *ztlo;
    __nv_bfloat16 *dhi, *dlo, *wdhi, *wdlo, *zhi, *zlo, *avhi, *avlo;
    __nv_bfloat16 *ehi, *elo, *wihhi, *wihlo, *wchi, *wclo;
    cudaGetSymbolAddress((void**)&embproj, g_embproj);
    cudaGetSymbolAddress((void**)&zbuf,    g_z);
    cudaGetSymbolAddress((void**)&Pbuf,    g_P);
    cudaGetSymbolAddress((void**)&decbuf,  g_dec);
    cudaGetSymbolAddress((void**)&phi,     g_P_hi);
    cudaGetSymbolAddress((void**)&plo,     g_P_lo);
    cudaGetSymbolAddress((void**)&zthi,    g_zT_hi);
    cudaGetSymbolAddress((void**)&ztlo,    g_zT_lo);
    cudaGetSymbolAddress((void**)&dhi,     g_dec_hi);
    cudaGetSymbolAddress((void**)&dlo,     g_dec_lo);
    cudaGetSymbolAddress((void**)&wdhi,    g_wd_hi);
    cudaGetSymbolAddress((void**)&wdlo,    g_wd_lo);
    cudaGetSymbolAddress((void**)&zhi,     g_z_hi);
    cudaGetSymbolAddress((void**)&zlo,     g_z_lo);
    cudaGetSymbolAddress((void**)&avhi,    g_av_hi);
    cudaGetSymbolAddress((void**)&avlo,    g_av_lo);
    cudaGetSymbolAddress((void**)&ehi,     g_emb_hi);
    cudaGetSymbolAddress((void**)&elo,     g_emb_lo);
    cudaGetSymbolAddress((void**)&wihhi,   g_wih_hi);
    cudaGetSymbolAddress((void**)&wihlo,   g_wih_lo);
    cudaGetSymbolAddress((void**)&wchi,    g_wc_hi);
    cudaGetSymbolAddress((void**)&wclo,    g_wc_lo);

    cudaFuncSetAttribute(hgemm_nt, cudaFuncAttributeMaxDynamicSharedMemorySize, HG_SMEM);

    static cudaStream_t s2 = nullptr;
    static cudaEvent_t evZ = nullptr, evT = nullptr, evDecZ = nullptr;
    if (!s2) {
        cudaStreamCreateWithFlags(&s2, cudaStreamNonBlocking);
        cudaEventCreateWithFlags(&evZ,    cudaEventDisableTiming);
        cudaEventCreateWithFlags(&evT,    cudaEventDisableTiming);
        cudaEventCreateWithFlags(&evDecZ, cudaEventDisableTiming);
    }

    const int ML = B_ * L_;   // 16384

    // ---- side stream: W_c / W_d splits overlap with the main head ----
    split_bf16<<<(H_ * 2 * H_ + 1023) / 1024, 1024, 0, s2>>>(W_c, wchi, wclo, H_ * 2 * H_);
    split_bf16<<<(V_ * H_ + 1023) / 1024, 1024, 0, s2>>>(W_d, wdhi, wdlo, V_ * H_);

    // ---- main: emb/W_ih splits -> embproj -> RNN ----
    split_bf16<<<(V_ * H_ + 1023) / 1024, 1024>>>(emb, ehi, elo, V_ * H_);
    split_bf16<<<(H_ * H_ + 1023) / 1024, 1024>>>(W_ih, wihhi, wihlo, H_ * H_);

    hgemm_nt<<<dim3(4, 79, 1), 256, HG_SMEM>>>(
        ehi, elo, H_, 0, wihhi, wihlo, H_, 0,
        embproj, nullptr, nullptr, H_, 0, V_, H_, H_, b_ih, 0);

    rnn_kernel<<<64, 512>>>(batch, embproj, W_hh, b_hh, zbuf, zhi, zlo);
    cudaEventRecord(evZ, 0);

    // ---- side branch: transpose + z-part decoder GEMM (with bias) ----
    cudaStreamWaitEvent(s2, evZ, 0);
    transpose_split<<<dim3(L_ / 32, H_ / 32, B_), 256, 0, s2>>>(zbuf, zthi, ztlo);
    cudaEventRecord(evT, s2);
    hgemm_nt<<<dim3(4, 128, 1), 256, HG_SMEM, s2>>>(
        zhi, zlo, H_, 0, wchi + H_, wclo + H_, 2 * H_, 0,
        decbuf, nullptr, nullptr, H_, 0, ML, H_, H_, b_c, 0);
    cudaEventRecord(evDecZ, s2);

    // ---- main branch: attention chain ----
    hgemm_nt<<<dim3(16, 16, B_), 256, HG_SMEM>>>(
        zhi, zlo, H_, LH, zhi, zlo, H_, LH,
        Pbuf, nullptr, nullptr, L_, LL, L_, L_, H_, nullptr, 2);

    softmax_rows<<<dim3(L_, B_), 256>>>(Pbuf, phi, plo);

    // av = P @ z^T  (causal K-limit, fused bf16-split output)
    cudaStreamWaitEvent(0, evT, 0);
    hgemm_nt<<<dim3(4, 16, B_), 256, HG_SMEM>>>(
        phi, plo, L_, LL, zthi, ztlo, L_, (long long)H_ * L_,
        nullptr, avhi, avlo, H_, LH, L_, H_, L_, nullptr, 4 | 8);

    // fix row 0: uniform attention -> mean of z, written as hi/lo
    av0_mean<<<B_, 512>>>(zbuf, avhi, avlo);

    // dec += av @ W_c[:, :H]^T  (accumulate fp32 dec, emit bf16 hi/lo)
    cudaStreamWaitEvent(0, evDecZ, 0);
    hgemm_nt<<<dim3(4, 128, 1), 256, HG_SMEM>>>(
        avhi, avlo, H_, 0, wchi, wclo, 2 * H_, 0,
        decbuf, dhi, dlo, H_, 0, ML, H_, H_, nullptr, 1 | 8);

    // logits = dec @ W_d^T + b_d
    hgemm_nt<<<dim3(79, 128, 1), 256, HG_SMEM>>>(
        dhi, dlo, H_, 0, wdhi, wdlo, H_, 0,
        out, nullptr, nullptr, V_, 0, ML, V_, H_, b_d, 0);
}